// round 6
// baseline (speedup 1.0000x reference)
#include <cuda_runtime.h>
#include <cuda_bf16.h>
#include <math.h>
#include <stdint.h>

// Problem dims
#define BD    128
#define SLEN  256
#define EDIM  512
#define HDIM  1024
#define ODIM  10
#define NG    4096
#define MTOT  (BD*SLEN)

#define NCTA  128
#define NTH   256

// ---------------------------------------------------------------------------
// Device scratch
// ---------------------------------------------------------------------------
__device__ int   g_is64;
// gatesx layout: [s][hb(128)][g(4)][b(128)][8]
__device__ float g_gatesx[(long)SLEN * BD * NG];
__device__ float g_h[BD * HDIM];

__device__ __nv_bfloat16 g_h_hi[2][BD * HDIM];
__device__ __nv_bfloat16 g_h_lo[2][BD * HDIM];
__device__ __nv_bfloat16 g_Whp_hi[(long)NG * HDIM];   // n = cta*32 + g*8 + j
__device__ __nv_bfloat16 g_Whp_lo[(long)NG * HDIM];
__device__ __nv_bfloat16 g_Wip_hi[(long)NG * EDIM];
__device__ __nv_bfloat16 g_Wip_lo[(long)NG * EDIM];
__device__ __nv_bfloat16 g_e_hi[(long)MTOT * EDIM];
__device__ __nv_bfloat16 g_e_lo[(long)MTOT * EDIM];

__device__ unsigned          g_bar_cnt[8 * 64];
__device__ volatile unsigned g_bar_gen[8 * 64];

// ---------------------------------------------------------------------------
__device__ __forceinline__ void bsplit(float v, __nv_bfloat16& hi, __nv_bfloat16& lo) {
    hi = __float2bfloat16_rn(v);
    lo = __float2bfloat16_rn(v - __bfloat162float(hi));
}

__device__ __forceinline__ void mma16816(float& d0, float& d1, float& d2, float& d3,
                                         uint32_t a0, uint32_t a1, uint32_t a2, uint32_t a3,
                                         uint32_t b0, uint32_t b1) {
    asm volatile("mma.sync.aligned.m16n8k16.row.col.f32.bf16.bf16.f32 "
                 "{%0,%1,%2,%3}, {%4,%5,%6,%7}, {%8,%9}, {%0,%1,%2,%3};"
                 : "+f"(d0), "+f"(d1), "+f"(d2), "+f"(d3)
                 : "r"(a0), "r"(a1), "r"(a2), "r"(a3), "r"(b0), "r"(b1));
}

__device__ __forceinline__ void ldsm4(uint32_t& r0, uint32_t& r1, uint32_t& r2,
                                      uint32_t& r3, uint32_t addr) {
    asm volatile("ldmatrix.sync.aligned.m8n8.x4.shared.b16 {%0,%1,%2,%3}, [%4];"
                 : "=r"(r0), "=r"(r1), "=r"(r2), "=r"(r3) : "r"(addr));
}

__device__ __forceinline__ void cpa16(uint32_t s, const void* g) {
    asm volatile("cp.async.cg.shared.global [%0], [%1], 16;\n" :: "r"(s), "l"(g));
}
#define CP_COMMIT() asm volatile("cp.async.commit_group;\n" ::: "memory")
template <int N> __device__ __forceinline__ void cp_wait() {
    asm volatile("cp.async.wait_group %0;\n" :: "n"(N) : "memory");
}

#define SWZ128(x) ((x) ^ (((x) >> 3) & 0x70))

// ---------------------------------------------------------------------------
__global__ void k_detect(const int* __restrict__ xw) {
    if (threadIdx.x == 0 && blockIdx.x == 0) {
        int zeros = 0;
        for (int i = 0; i < 64; i++)
            if (xw[2 * i + 1] == 0) zeros++;
        g_is64 = (zeros >= 60) ? 1 : 0;
    }
}

__global__ void k_init() {
    int i = blockIdx.x * blockDim.x + threadIdx.x;
    if (i < BD * HDIM) {
        g_h_hi[0][i] = __float2bfloat16(0.f);
        g_h_lo[0][i] = __float2bfloat16(0.f);
    }
    if (i < 8 * 64) {
        g_bar_cnt[i] = 0u;
        g_bar_gen[i] = 0u;
    }
}

__global__ void k_emb_split(const void* __restrict__ xv, const float* __restrict__ emb) {
    int m = blockIdx.x;
    long tok = g_is64 ? (long)((const long long*)xv)[m] : (long)((const int*)xv)[m];
    const float* src = emb + tok * EDIM;
    for (int k = threadIdx.x; k < EDIM; k += blockDim.x) {
        __nv_bfloat16 hi, lo;
        bsplit(src[k], hi, lo);
        g_e_hi[(long)m * EDIM + k] = hi;
        g_e_lo[(long)m * EDIM + k] = lo;
    }
}

__global__ void k_pack_wi(const float* __restrict__ Wi, const float* __restrict__ Wf,
                          const float* __restrict__ Wg, const float* __restrict__ Wo) {
    int n = blockIdx.x;
    int g = n >> 10, col = n & 1023;
    const float* src = ((g == 0) ? Wi : (g == 1) ? Wf : (g == 2) ? Wg : Wo) + (long)col * EDIM;
    for (int k = threadIdx.x; k < EDIM; k += blockDim.x) {
        __nv_bfloat16 hi, lo;
        bsplit(src[k], hi, lo);
        g_Wip_hi[(long)n * EDIM + k] = hi;
        g_Wip_lo[(long)n * EDIM + k] = lo;
    }
}

// n = cta*32 + g*8 + j ; hidden h = cta*8 + j
__global__ void k_pack_wh(const float* __restrict__ Wi, const float* __restrict__ Wf,
                          const float* __restrict__ Wg, const float* __restrict__ Wo) {
    int n = blockIdx.x;
    int hb = n >> 5, r = n & 31, g = r >> 3, j = r & 7;
    int h = hb * 8 + j;
    const float* src = ((g == 0) ? Wi : (g == 1) ? Wf : (g == 2) ? Wg : Wo) + (long)h * HDIM;
    for (int k = threadIdx.x; k < HDIM; k += blockDim.x) {
        __nv_bfloat16 hi, lo;
        bsplit(src[k], hi, lo);
        g_Whp_hi[(long)n * HDIM + k] = hi;
        g_Whp_lo[(long)n * HDIM + k] = lo;
    }
}

// ---------------------------------------------------------------------------
// Input projection GEMM (legacy tensor cores, unchanged from R4)
// ---------------------------------------------------------------------------
#define IP 24
__global__ __launch_bounds__(256)
void k_igemm_tc(const float* __restrict__ bi, const float* __restrict__ bf2,
                const float* __restrict__ bg, const float* __restrict__ bo) {
    __shared__ __align__(16) __nv_bfloat16 sm[2][4][128 * IP];

    const int tid = threadIdx.x;
    const int n0 = blockIdx.x * 128;
    const int M0 = blockIdx.y * 128;

    const int w = tid >> 5, lane = tid & 31;
    const int g = lane >> 2, tig = lane & 3;
    const int m0w = (w >> 1) * 32, n0w = (w & 1) * 64;

    const __nv_bfloat16* gp[2];
    int sel[2], idx[2];
#pragma unroll
    for (int a = 0; a < 2; a++) {
        int r = tid + a * 256;
        sel[a] = r >> 7; idx[a] = r & 127;
        if (sel[a] == 0)      gp[a] = g_e_hi   + (long)(M0 + idx[a]) * EDIM;
        else if (sel[a] == 1) gp[a] = g_e_lo   + (long)(M0 + idx[a]) * EDIM;
        else if (sel[a] == 2) gp[a] = g_Wip_hi + (long)(n0 + idx[a]) * EDIM;
        else                  gp[a] = g_Wip_lo + (long)(n0 + idx[a]) * EDIM;
    }

    float acc[2][8][4];
#pragma unroll
    for (int mt = 0; mt < 2; mt++)
#pragma unroll
        for (int nt = 0; nt < 8; nt++)
#pragma unroll
            for (int q = 0; q < 4; q++) acc[mt][nt][q] = 0.f;

    uint4 p[2][2];
#pragma unroll
    for (int a = 0; a < 2; a++) { p[a][0] = ((const uint4*)gp[a])[0]; p[a][1] = ((const uint4*)gp[a])[1]; }
#pragma unroll
    for (int a = 0; a < 2; a++) {
        uint4* d = (uint4*)(&sm[0][sel[a]][idx[a] * IP]);
        d[0] = p[a][0]; d[1] = p[a][1];
    }
    __syncthreads();

    const int NSTAGE = EDIM / 16;
    for (int s = 0; s < NSTAGE; s++) {
        int buf = s & 1;
        bool more = (s + 1 < NSTAGE);
        if (more) {
#pragma unroll
            for (int a = 0; a < 2; a++) {
                gp[a] += 16;
                p[a][0] = ((const uint4*)gp[a])[0]; p[a][1] = ((const uint4*)gp[a])[1];
            }
        }
        const __nv_bfloat16* Ah = sm[buf][0];
        const __nv_bfloat16* Al = sm[buf][1];
        const __nv_bfloat16* Bh = sm[buf][2];
        const __nv_bfloat16* Bl = sm[buf][3];
        const int kb = 2 * tig;

        uint32_t aH[2][4], aL[2][4], bH[8][2], bL[8][2];
#pragma unroll
        for (int mt = 0; mt < 2; mt++) {
            int rw = (m0w + mt * 16 + g) * IP + kb;
            aH[mt][0] = *(const uint32_t*)(Ah + rw);
            aH[mt][1] = *(const uint32_t*)(Ah + rw + 8 * IP);
            aH[mt][2] = *(const uint32_t*)(Ah + rw + 8);
            aH[mt][3] = *(const uint32_t*)(Ah + rw + 8 * IP + 8);
            aL[mt][0] = *(const uint32_t*)(Al + rw);
            aL[mt][1] = *(const uint32_t*)(Al + rw + 8 * IP);
            aL[mt][2] = *(const uint32_t*)(Al + rw + 8);
            aL[mt][3] = *(const uint32_t*)(Al + rw + 8 * IP + 8);
        }
#pragma unroll
        for (int nt = 0; nt < 8; nt++) {
            int cw = (n0w + nt * 8 + g) * IP + kb;
            bH[nt][0] = *(const uint32_t*)(Bh + cw);
            bH[nt][1] = *(const uint32_t*)(Bh + cw + 8);
            bL[nt][0] = *(const uint32_t*)(Bl + cw);
            bL[nt][1] = *(const uint32_t*)(Bl + cw + 8);
        }
#pragma unroll
        for (int mt = 0; mt < 2; mt++)
#pragma unroll
            for (int nt = 0; nt < 8; nt++) {
                float* d = acc[mt][nt];
                mma16816(d[0], d[1], d[2], d[3], aH[mt][0], aH[mt][1], aH[mt][2], aH[mt][3], bH[nt][0], bH[nt][1]);
                mma16816(d[0], d[1], d[2], d[3], aL[mt][0], aL[mt][1], aL[mt][2], aL[mt][3], bH[nt][0], bH[nt][1]);
                mma16816(d[0], d[1], d[2], d[3], aH[mt][0], aH[mt][1], aH[mt][2], aH[mt][3], bL[nt][0], bL[nt][1]);
            }

        if (more) {
#pragma unroll
            for (int a = 0; a < 2; a++) {
                uint4* d = (uint4*)(&sm[buf ^ 1][sel[a]][idx[a] * IP]);
                d[0] = p[a][0]; d[1] = p[a][1];
            }
        }
        __syncthreads();
    }

#pragma unroll
    for (int mt = 0; mt < 2; mt++) {
        int r0 = m0w + mt * 16 + g;
#pragma unroll
        for (int nt = 0; nt < 8; nt++) {
            int col  = n0w + nt * 8 + 2 * tig;
            int ncol = n0 + col;
            int gate = ncol >> 10, hcol = ncol & 1023;
            int hb = hcol >> 3, j = hcol & 7;
            const float* bptr = (gate == 0) ? bi : (gate == 1) ? bf2 : (gate == 2) ? bg : bo;
            float bv0 = bptr[hcol], bv1 = bptr[hcol + 1];
#pragma unroll
            for (int half = 0; half < 2; half++) {
                int mrow = M0 + r0 + half * 8;
                int b = mrow >> 8, ss = mrow & 255;
                float2 v = make_float2(acc[mt][nt][half * 2] + bv0, acc[mt][nt][half * 2 + 1] + bv1);
                long off = ((((long)ss * 128 + hb) * 4 + gate) * 128 + b) * 8 + j;
                *(float2*)(g_gatesx + off) = v;
            }
        }
    }
}

// ---------------------------------------------------------------------------
// Persistent LSTM step kernel v3 (legacy HMMA + ldmatrix, register epilogue).
// 128 CTAs x 256 thr. Warp w: M rows [w*16, w*16+16), all N=32 (4 gates x 8).
// W (hi+lo) resident in SMEM SW128 layout; h streamed kc=64, 3-ring, 1 sync
// per chunk; c + gates in registers; register-local cell update.
// ---------------------------------------------------------------------------
#define SM_W   0
#define SM_A   131072
#define SMEM_TC3 (131072 + 3*32768)   // 229376

__device__ __forceinline__ void gridbar(unsigned gen) {
    __syncthreads();
    if (threadIdx.x == 0) {
        __threadfence();
        int c = (blockIdx.x & 7) * 64;
        unsigned prev = atomicAdd(&g_bar_cnt[c], 1u);
        if (prev == (NCTA / 8) - 1) {
            g_bar_cnt[c] = 0u;
            __threadfence();
            g_bar_gen[c] = gen;
        }
    }
    if (threadIdx.x < 8) {
        while (g_bar_gen[threadIdx.x * 64] < gen) { }
        __threadfence();
    }
    __syncthreads();
}

__global__ __launch_bounds__(NTH, 1)
void k_step3() {
    extern __shared__ __align__(1024) unsigned char smraw[];
    const uint32_t sb = (uint32_t)__cvta_generic_to_shared(smraw);

    const int tid = threadIdx.x;
    const int cta = blockIdx.x;
    const int w = tid >> 5, lane = tid & 31;

    // ---- resident weights -> SMEM (SW128 blocked-atom [32n][1024k]) ----
    {
        const int p = tid >> 7;
        const __nv_bfloat16* wsrc = (p ? g_Whp_lo : g_Whp_hi) + (long)cta * 32 * HDIM;
        unsigned char* wdst = smraw + SM_W + p * 65536;
        for (int idx = tid & 127; idx < 32 * 128; idx += 128) {
            int r = idx >> 7, cc = idx & 127;
            int c0 = cc * 8;
            uint32_t byte = (uint32_t)(((r >> 3) + (c0 >> 6) * 4) * 1024 + (r & 7) * 128 + (c0 & 63) * 2);
            *(uint4*)(wdst + SWZ128(byte)) = *(const uint4*)(wsrc + r * HDIM + c0);
        }
    }

    // ---- ldmatrix lane address components ----
    // A (m16k16, x4): M0 rows0-7/k0-7, M1 rows8-15/k0-7, M2 rows0-7/k8-15, M3 rows8-15/k8-15
    const int aq = lane >> 3, al = lane & 7;
    const int am = w * 16 + ((aq & 1) ? 8 : 0) + al;
    const uint32_t akb = (uint32_t)((aq >> 1) * 16);                 // +16B if k+8 half
    const uint32_t aR  = (uint32_t)((am >> 3) * 1024 + (am & 7) * 128);
    const uint32_t aC  = (uint32_t)((am & 7) * 16);
    // B from W ([32n][1024k]): per pair p: M0 nt rows/k0-7, M1 nt/k8-15, M2 nt+1/k0-7, M3 nt+1/k8-15
    const int bq = lane >> 3, bl = lane & 7;
    const int bn_off = (bq >> 1) * 8;
    const uint32_t bkb = (uint32_t)((bq & 1) * 16);
    uint32_t bR[2], bC[2];
#pragma unroll
    for (int p = 0; p < 2; p++) {
        int n = p * 16 + bn_off + bl;
        bR[p] = (uint32_t)((n >> 3) * 1024 + (n & 7) * 128);
        bC[p] = (uint32_t)((n & 7) * 16);
    }

    // loader mapping
    const int prec = tid >> 7;
    const int lrow = tid & 127;
    const uint32_t rowoff = (uint32_t)((lrow >> 3) * 1024 + (lrow & 7) * 128);

    // epilogue mapping
    const int er = lane >> 2, ec = (lane & 3) * 2;
    const int b0 = w * 16 + er;

    float creg[2][2];
    creg[0][0] = creg[0][1] = creg[1][0] = creg[1][1] = 0.f;

    __syncthreads();

    for (int t = 0; t < SLEN; t++) {
        const int par = t & 1, nxt = par ^ 1;
        const __nv_bfloat16* hsrc =
            (prec ? g_h_lo[par] : g_h_hi[par]) + (long)lrow * HDIM;

        // prologue: chunks 0,1
#pragma unroll
        for (int c = 0; c < 2; c++) {
            uint32_t dst = sb + SM_A + c * 32768 + prec * 16384;
            const __nv_bfloat16* src = hsrc + c * 64;
#pragma unroll
            for (int i = 0; i < 8; i++)
                cpa16(dst + SWZ128(rowoff + i * 16), src + i * 8);
            CP_COMMIT();
        }

        // gates preload (register, off critical path)
        float2 gv[4][2];
        {
            const float* gx = g_gatesx + ((long)(t * 128 + cta) * 4) * 1024;
#pragma unroll
            for (int g = 0; g < 4; g++) {
                gv[g][0] = *(const float2*)(gx + (g * 128 + b0) * 8 + ec);
                gv[g][1] = *(const float2*)(gx + (g * 128 + b0 + 8) * 8 + ec);
            }
        }

        float acc[4][4];
#pragma unroll
        for (int nt = 0; nt < 4; nt++)
#pragma unroll
            for (int q = 0; q < 4; q++) acc[nt][q] = 0.f;

        for (int s = 0; s < 16; s++) {
            if (s >= 14) CP_COMMIT();     // empty group so wait<1> forces chunk s
            cp_wait<1>();
            __syncthreads();

            if (s + 2 < 16) {
                uint32_t dst = sb + SM_A + ((s + 2) % 3) * 32768 + prec * 16384;
                const __nv_bfloat16* src = hsrc + (s + 2) * 64;
#pragma unroll
                for (int i = 0; i < 8; i++)
                    cpa16(dst + SWZ128(rowoff + i * 16), src + i * 8);
                CP_COMMIT();
            }

            const uint32_t aHi = sb + SM_A + (s % 3) * 32768;
            const uint32_t aLo = aHi + 16384;
            const uint32_t wHi = sb + SM_W + (uint32_t)s * 4096;
            const uint32_t wLo = wHi + 65536;

#pragma unroll
            for (int kt = 0; kt < 4; kt++) {
                const uint32_t ka = (uint32_t)(kt * 32);
                uint32_t ah[4], alr[4];
                ldsm4(ah[0], ah[1], ah[2], ah[3],   aHi + aR + ((ka + akb) ^ aC));
                ldsm4(alr[0], alr[1], alr[2], alr[3], aLo + aR + ((ka + akb) ^ aC));
#pragma unroll
                for (int p = 0; p < 2; p++) {
                    uint32_t bh[4], blr[4];
                    ldsm4(bh[0], bh[1], bh[2], bh[3],   wHi + bR[p] + ((ka + bkb) ^ bC[p]));
                    ldsm4(blr[0], blr[1], blr[2], blr[3], wLo + bR[p] + ((ka + bkb) ^ bC[p]));
#pragma unroll
                    for (int h2 = 0; h2 < 2; h2++) {
                        float* d = acc[p * 2 + h2];
                        mma16816(d[0], d[1], d[2], d[3], ah[0], ah[1], ah[2], ah[3], bh[h2 * 2], bh[h2 * 2 + 1]);
                        mma16816(d[0], d[1], d[2], d[3], alr[0], alr[1], alr[2], alr[3], bh[h2 * 2], bh[h2 * 2 + 1]);
                        mma16816(d[0], d[1], d[2], d[3], ah[0], ah[1], ah[2], ah[3], blr[h2 * 2], blr[h2 * 2 + 1]);
                    }
                }
            }
        }

        // register-local cell update: rows b0, b0+8; cols cta*8 + ec + {0,1}
#pragma unroll
        for (int h2 = 0; h2 < 2; h2++) {
            const int bb = b0 + h2 * 8;
            float hn[2];
            __nv_bfloat16 hh[2], hl[2];
#pragma unroll
            for (int q = 0; q < 2; q++) {
                float pi = acc[0][h2 * 2 + q] + (q ? gv[0][h2].y : gv[0][h2].x);
                float pf = acc[1][h2 * 2 + q] + (q ? gv[1][h2].y : gv[1][h2].x);
                float pg = acc[2][h2 * 2 + q] + (q ? gv[2][h2].y : gv[2][h2].x);
                float po = acc[3][h2 * 2 + q] + (q ? gv[3][h2].y : gv[3][h2].x);
                float iv = 1.f / (1.f + expf(-pi));
                float fv = 1.f / (1.f + expf(-pf));
                float gg = tanhf(pg);
                float ov = 1.f / (1.f + expf(-po));
                float cn = fv * creg[h2][q] + iv * gg;
                creg[h2][q] = cn;
                hn[q] = ov * tanhf(cn);
                bsplit(hn[q], hh[q], hl[q]);
            }
            long hb = (long)bb * HDIM + cta * 8 + ec;
            *(__nv_bfloat162*)&g_h_hi[nxt][hb] = *(__nv_bfloat162*)hh;
            *(__nv_bfloat162*)&g_h_lo[nxt][hb] = *(__nv_bfloat162*)hl;
            if (t == SLEN - 1) *(float2*)&g_h[hb] = make_float2(hn[0], hn[1]);
        }

        gridbar((unsigned)(t + 1));
    }
}

// ---------------------------------------------------------------------------
__global__ void k_fc(const float* __restrict__ fcW, const float* __restrict__ fcb,
                     float* __restrict__ out) {
    int b = blockIdx.x;
    int w = threadIdx.x >> 5, lane = threadIdx.x & 31;
    if (w >= ODIM) return;
    const float* hrow = g_h + b * HDIM;
    const float* wrow = fcW + w * HDIM;
    float s = 0.f;
    for (int k = lane; k < HDIM; k += 32) s += hrow[k] * wrow[k];
#pragma unroll
    for (int off = 16; off; off >>= 1) s += __shfl_xor_sync(0xffffffffu, s, off);
    if (lane == 0) out[b * ODIM + w] = s + fcb[w];
}

// ---------------------------------------------------------------------------
extern "C" void kernel_launch(void* const* d_in, const int* in_sizes, int n_in,
                              void* d_out, int out_size) {
    const void*  x   = d_in[0];
    const float* emb = (const float*)d_in[1];
    const float* Wii = (const float*)d_in[2];
    const float* bii = (const float*)d_in[3];
    const float* Whi = (const float*)d_in[4];
    const float* Wif = (const float*)d_in[5];
    const float* bif = (const float*)d_in[6];
    const float* Whf = (const float*)d_in[7];
    const float* Wig = (const float*)d_in[8];
    const float* big = (const float*)d_in[9];
    const float* Whg = (const float*)d_in[10];
    const float* Wio = (const float*)d_in[11];
    const float* bio = (const float*)d_in[12];
    const float* Who = (const float*)d_in[13];
    const float* fcW = (const float*)d_in[14];
    const float* fcb = (const float*)d_in[15];
    float* out = (float*)d_out;

    cudaFuncSetAttribute(k_step3, cudaFuncAttributeMaxDynamicSharedMemorySize,
                         SMEM_TC3);

    k_detect<<<1, 32>>>((const int*)x);
    k_init<<<(BD * HDIM + 255) / 256, 256>>>();
    k_emb_split<<<MTOT, 128>>>(x, emb);
    k_pack_wi<<<NG, 256>>>(Wii, Wif, Wig, Wio);
    k_pack_wh<<<NG, 256>>>(Whi, Whf, Whg, Who);

    k_igemm_tc<<<dim3(NG / 128, MTOT / 128), 256>>>(bii, bif, big, bio);

    k_step3<<<NCTA, NTH, SMEM_TC3>>>();

    k_fc<<<BD, 320>>>(fcW, fcb, out);
}

// round 7
// speedup vs baseline: 1.1595x; 1.1595x over previous
#include <cuda_runtime.h>
#include <cuda_fp16.h>
#include <math.h>
#include <stdint.h>

// Problem dims
#define BD    128
#define SLEN  256
#define EDIM  512
#define HDIM  1024
#define ODIM  10
#define NG    4096
#define MTOT  (BD*SLEN)

#define NCTA  128
#define NTH   256

// ---------------------------------------------------------------------------
// Device scratch
// ---------------------------------------------------------------------------
// gatesx layout: [s][hb(128)][g(4)][b(128)][8]
__device__ float g_gatesx[(long)SLEN * BD * NG];
__device__ float g_h[BD * HDIM];

__device__ __half g_h_hi[2][BD * HDIM];
__device__ __half g_h_lo[2][BD * HDIM];
__device__ __half g_Whp[(long)NG * HDIM];   // fp16 W, n = cta*32 + g*8 + j
__device__ __half g_Wip[(long)NG * EDIM];   // fp16 W, n = g*1024 + col
__device__ __half g_e_hi[(long)MTOT * EDIM];
__device__ __half g_e_lo[(long)MTOT * EDIM];

__device__ unsigned          g_bar_cnt[8 * 64];
__device__ volatile unsigned g_bar_gen[8 * 64];

// ---------------------------------------------------------------------------
__device__ __forceinline__ void hsplit(float v, __half& hi, __half& lo) {
    hi = __float2half_rn(v);
    lo = __float2half_rn(v - __half2float(hi));
}

__device__ __forceinline__ void mma16816(float& d0, float& d1, float& d2, float& d3,
                                         uint32_t a0, uint32_t a1, uint32_t a2, uint32_t a3,
                                         uint32_t b0, uint32_t b1) {
    asm volatile("mma.sync.aligned.m16n8k16.row.col.f32.f16.f16.f32 "
                 "{%0,%1,%2,%3}, {%4,%5,%6,%7}, {%8,%9}, {%0,%1,%2,%3};"
                 : "+f"(d0), "+f"(d1), "+f"(d2), "+f"(d3)
                 : "r"(a0), "r"(a1), "r"(a2), "r"(a3), "r"(b0), "r"(b1));
}

__device__ __forceinline__ void ldsm4(uint32_t& r0, uint32_t& r1, uint32_t& r2,
                                      uint32_t& r3, uint32_t addr) {
    asm volatile("ldmatrix.sync.aligned.m8n8.x4.shared.b16 {%0,%1,%2,%3}, [%4];"
                 : "=r"(r0), "=r"(r1), "=r"(r2), "=r"(r3) : "r"(addr));
}

__device__ __forceinline__ void cpa16(uint32_t s, const void* g) {
    asm volatile("cp.async.cg.shared.global [%0], [%1], 16;\n" :: "r"(s), "l"(g));
}
#define CP_COMMIT() asm volatile("cp.async.commit_group;\n" ::: "memory")
template <int N> __device__ __forceinline__ void cp_wait() {
    asm volatile("cp.async.wait_group %0;\n" :: "n"(N) : "memory");
}

#define SWZ128(x) ((x) ^ (((x) >> 3) & 0x70))

// ---------------------------------------------------------------------------
// prepA: blocks [0, MTOT): embedding gather + fp16 split (per-block dtype
// detect, no cross-block dependency). Blocks [MTOT, MTOT+512): init h/c/bars.
// ---------------------------------------------------------------------------
__global__ void k_prepA(const void* __restrict__ xv, const float* __restrict__ emb) {
    const int blk = blockIdx.x;
    const int tid = threadIdx.x;
    if (blk < MTOT) {
        __shared__ int s64;
        if (tid == 0) {
            const int* xw = (const int*)xv;
            int zeros = 0;
            for (int i = 0; i < 64; i++)
                if (xw[2 * i + 1] == 0) zeros++;
            s64 = (zeros >= 60) ? 1 : 0;
        }
        __syncthreads();
        long tok = s64 ? (long)((const long long*)xv)[blk] : (long)((const int*)xv)[blk];
        const float* src = emb + tok * EDIM;
        for (int k = tid; k < EDIM; k += blockDim.x) {
            __half hi, lo;
            hsplit(src[k], hi, lo);
            g_e_hi[(long)blk * EDIM + k] = hi;
            g_e_lo[(long)blk * EDIM + k] = lo;
        }
    } else {
        int i = (blk - MTOT) * 256 + tid;
        if (i < BD * HDIM) {
            g_h_hi[0][i] = __float2half(0.f);
            g_h_lo[0][i] = __float2half(0.f);
        }
        if (i < 8 * 64) {
            g_bar_cnt[i] = 0u;
            g_bar_gen[i] = 0u;
        }
    }
}

// prepB: blocks [0, NG): pack input W (fp16). Blocks [NG, 2*NG): pack recurrent W.
__global__ void k_prepB(const float* __restrict__ Wii, const float* __restrict__ Wif,
                        const float* __restrict__ Wig, const float* __restrict__ Wio,
                        const float* __restrict__ Whi, const float* __restrict__ Whf,
                        const float* __restrict__ Whg, const float* __restrict__ Who) {
    const int blk = blockIdx.x;
    if (blk < NG) {
        int n = blk;
        int g = n >> 10, col = n & 1023;
        const float* src = ((g == 0) ? Wii : (g == 1) ? Wif : (g == 2) ? Wig : Wio)
                           + (long)col * EDIM;
        for (int k = threadIdx.x; k < EDIM; k += blockDim.x)
            g_Wip[(long)n * EDIM + k] = __float2half_rn(src[k]);
    } else {
        int n = blk - NG;
        int hb = n >> 5, r = n & 31, g = r >> 3, j = r & 7;
        int h = hb * 8 + j;
        const float* src = ((g == 0) ? Whi : (g == 1) ? Whf : (g == 2) ? Whg : Who)
                           + (long)h * HDIM;
        for (int k = threadIdx.x; k < HDIM; k += blockDim.x)
            g_Whp[(long)n * HDIM + k] = __float2half_rn(src[k]);
    }
}

// ---------------------------------------------------------------------------
// Input projection GEMM: [32768 x 512] @ [512 x 4096], fp16 2-term.
// CTA tile 128x128, 256 threads, kc=16, 2-stage. Regions: Ah, Al, B.
// ---------------------------------------------------------------------------
#define IP 24
__global__ __launch_bounds__(256)
void k_igemm_tc(const float* __restrict__ bi, const float* __restrict__ bf2,
                const float* __restrict__ bg, const float* __restrict__ bo) {
    __shared__ __align__(16) __half sm[2][3][128 * IP];

    const int tid = threadIdx.x;
    const int n0 = blockIdx.x * 128;
    const int M0 = blockIdx.y * 128;

    const int w = tid >> 5, lane = tid & 31;
    const int g = lane >> 2, tig = lane & 3;
    const int m0w = (w >> 1) * 32, n0w = (w & 1) * 64;

    // copy plan: 384 rows of 32B per stage. r0 = tid (Ah/Al); rB = tid (B, tid<128)
    const int sel0 = tid >> 7, idx0 = tid & 127;
    const __half* gp0 = (sel0 ? g_e_lo : g_e_hi) + (long)(M0 + idx0) * EDIM;
    const bool hasB = (tid < 128);
    const __half* gpB = g_Wip + (long)(n0 + tid) * EDIM;

    float acc[2][8][4];
#pragma unroll
    for (int mt = 0; mt < 2; mt++)
#pragma unroll
        for (int nt = 0; nt < 8; nt++)
#pragma unroll
            for (int q = 0; q < 4; q++) acc[mt][nt][q] = 0.f;

    uint4 p0[2], pB[2];
    p0[0] = ((const uint4*)gp0)[0]; p0[1] = ((const uint4*)gp0)[1];
    if (hasB) { pB[0] = ((const uint4*)gpB)[0]; pB[1] = ((const uint4*)gpB)[1]; }
    {
        uint4* d = (uint4*)(&sm[0][sel0][idx0 * IP]);
        d[0] = p0[0]; d[1] = p0[1];
        if (hasB) {
            uint4* d2 = (uint4*)(&sm[0][2][tid * IP]);
            d2[0] = pB[0]; d2[1] = pB[1];
        }
    }
    __syncthreads();

    const int NSTAGE = EDIM / 16;
    for (int s = 0; s < NSTAGE; s++) {
        int buf = s & 1;
        bool more = (s + 1 < NSTAGE);
        if (more) {
            gp0 += 16;
            p0[0] = ((const uint4*)gp0)[0]; p0[1] = ((const uint4*)gp0)[1];
            if (hasB) {
                gpB += 16;
                pB[0] = ((const uint4*)gpB)[0]; pB[1] = ((const uint4*)gpB)[1];
            }
        }
        const __half* Ah = sm[buf][0];
        const __half* Al = sm[buf][1];
        const __half* Bm = sm[buf][2];
        const int kb = 2 * tig;

        uint32_t aH[2][4], aL[2][4], bF[8][2];
#pragma unroll
        for (int mt = 0; mt < 2; mt++) {
            int rw = (m0w + mt * 16 + g) * IP + kb;
            aH[mt][0] = *(const uint32_t*)(Ah + rw);
            aH[mt][1] = *(const uint32_t*)(Ah + rw + 8 * IP);
            aH[mt][2] = *(const uint32_t*)(Ah + rw + 8);
            aH[mt][3] = *(const uint32_t*)(Ah + rw + 8 * IP + 8);
            aL[mt][0] = *(const uint32_t*)(Al + rw);
            aL[mt][1] = *(const uint32_t*)(Al + rw + 8 * IP);
            aL[mt][2] = *(const uint32_t*)(Al + rw + 8);
            aL[mt][3] = *(const uint32_t*)(Al + rw + 8 * IP + 8);
        }
#pragma unroll
        for (int nt = 0; nt < 8; nt++) {
            int cw = (n0w + nt * 8 + g) * IP + kb;
            bF[nt][0] = *(const uint32_t*)(Bm + cw);
            bF[nt][1] = *(const uint32_t*)(Bm + cw + 8);
        }
#pragma unroll
        for (int mt = 0; mt < 2; mt++)
#pragma unroll
            for (int nt = 0; nt < 8; nt++) {
                float* d = acc[mt][nt];
                mma16816(d[0], d[1], d[2], d[3], aH[mt][0], aH[mt][1], aH[mt][2], aH[mt][3], bF[nt][0], bF[nt][1]);
                mma16816(d[0], d[1], d[2], d[3], aL[mt][0], aL[mt][1], aL[mt][2], aL[mt][3], bF[nt][0], bF[nt][1]);
            }

        if (more) {
            uint4* d = (uint4*)(&sm[buf ^ 1][sel0][idx0 * IP]);
            d[0] = p0[0]; d[1] = p0[1];
            if (hasB) {
                uint4* d2 = (uint4*)(&sm[buf ^ 1][2][tid * IP]);
                d2[0] = pB[0]; d2[1] = pB[1];
            }
        }
        __syncthreads();
    }

    // epilogue: add bias, write [s][hb][g][b][8]
#pragma unroll
    for (int mt = 0; mt < 2; mt++) {
        int r0 = m0w + mt * 16 + g;
#pragma unroll
        for (int nt = 0; nt < 8; nt++) {
            int col  = n0w + nt * 8 + 2 * tig;
            int ncol = n0 + col;
            int gate = ncol >> 10, hcol = ncol & 1023;
            int hb = hcol >> 3, j = hcol & 7;
            const float* bptr = (gate == 0) ? bi : (gate == 1) ? bf2 : (gate == 2) ? bg : bo;
            float bv0 = bptr[hcol], bv1 = bptr[hcol + 1];
#pragma unroll
            for (int half2_ = 0; half2_ < 2; half2_++) {
                int mrow = M0 + r0 + half2_ * 8;
                int b = mrow >> 8, ss = mrow & 255;
                float2 v = make_float2(acc[mt][nt][half2_ * 2] + bv0, acc[mt][nt][half2_ * 2 + 1] + bv1);
                long off = ((((long)ss * 128 + hb) * 4 + gate) * 128 + b) * 8 + j;
                *(float2*)(g_gatesx + off) = v;
            }
        }
    }
}

// ---------------------------------------------------------------------------
// Persistent LSTM step kernel (fp16 2-term, ldmatrix, register epilogue).
// ---------------------------------------------------------------------------
#define SM_A   0
#define SM_W   131072                  // 4 A bufs x 32KB
#define SMEM_TC3 (131072 + 65536)      // 196608

__device__ __forceinline__ void gridbar(unsigned gen) {
    __syncthreads();
    if (threadIdx.x == 0) {
        __threadfence();
        int c = (blockIdx.x & 7) * 64;
        unsigned prev = atomicAdd(&g_bar_cnt[c], 1u);
        if (prev == (NCTA / 8) - 1) {
            g_bar_cnt[c] = 0u;
            __threadfence();
            g_bar_gen[c] = gen;
        }
    }
    if (threadIdx.x < 8) {
        while (g_bar_gen[threadIdx.x * 64] < gen) { }
        __threadfence();
    }
    __syncthreads();
}

__global__ __launch_bounds__(NTH, 1)
void k_step3() {
    extern __shared__ __align__(1024) unsigned char smraw[];
    const uint32_t sb = (uint32_t)__cvta_generic_to_shared(smraw);

    const int tid = threadIdx.x;
    const int cta = blockIdx.x;
    const int w = tid >> 5, lane = tid & 31;

    // ---- resident W (fp16, 32x1024) -> SMEM SW128 blocked-atom ----
    {
        const __half* wsrc = g_Whp + (long)cta * 32 * HDIM;
        unsigned char* wdst = smraw + SM_W;
        for (int idx = tid; idx < 32 * 128; idx += NTH) {
            int r = idx >> 7, cc = idx & 127;
            int c0 = cc * 8;
            uint32_t byte = (uint32_t)(((r >> 3) + (c0 >> 6) * 4) * 1024 + (r & 7) * 128 + (c0 & 63) * 2);
            *(uint4*)(wdst + SWZ128(byte)) = *(const uint4*)(wsrc + r * HDIM + c0);
        }
    }

    // ---- ldmatrix lane address components ----
    const int aq = lane >> 3, al = lane & 7;
    const int am = w * 16 + ((aq & 1) ? 8 : 0) + al;
    const uint32_t akb = (uint32_t)((aq >> 1) * 16);
    const uint32_t aR  = (uint32_t)((am >> 3) * 1024 + (am & 7) * 128);
    const uint32_t aC  = (uint32_t)((am & 7) * 16);
    const int bq = lane >> 3, bl = lane & 7;
    const int bn_off = (bq >> 1) * 8;
    const uint32_t bkb = (uint32_t)((bq & 1) * 16);
    uint32_t bR[2], bC[2];
#pragma unroll
    for (int p = 0; p < 2; p++) {
        int n = p * 16 + bn_off + bl;
        bR[p] = (uint32_t)((n >> 3) * 1024 + (n & 7) * 128);
        bC[p] = (uint32_t)((n & 7) * 16);
    }

    // loader mapping: prec = tid>>7 (0 hi, 1 lo), row = tid&127
    const int prec = tid >> 7;
    const int lrow = tid & 127;
    const uint32_t rowoff = (uint32_t)((lrow >> 3) * 1024 + (lrow & 7) * 128);

    // epilogue mapping
    const int er = lane >> 2, ec = (lane & 3) * 2;
    const int b0 = w * 16 + er;

    float creg[2][2];
    creg[0][0] = creg[0][1] = creg[1][0] = creg[1][1] = 0.f;

    __syncthreads();

    for (int t = 0; t < SLEN; t++) {
        const int par = t & 1, nxt = par ^ 1;
        const __half* hsrc = (prec ? g_h_lo[par] : g_h_hi[par]) + (long)lrow * HDIM;

        // prologue: chunks 0,1,2
#pragma unroll
        for (int c = 0; c < 3; c++) {
            uint32_t dst = sb + SM_A + c * 32768 + prec * 16384;
            const __half* src = hsrc + c * 64;
#pragma unroll
            for (int i = 0; i < 8; i++)
                cpa16(dst + SWZ128(rowoff + i * 16), src + i * 8);
            CP_COMMIT();
        }

        // gates preload into registers
        float2 gv[4][2];
        {
            const float* gx = g_gatesx + ((long)(t * 128 + cta) * 4) * 1024;
#pragma unroll
            for (int g = 0; g < 4; g++) {
                gv[g][0] = *(const float2*)(gx + (g * 128 + b0) * 8 + ec);
                gv[g][1] = *(const float2*)(gx + (g * 128 + b0 + 8) * 8 + ec);
            }
        }

        float acc[4][4];
#pragma unroll
        for (int nt = 0; nt < 4; nt++)
#pragma unroll
            for (int q = 0; q < 4; q++) acc[nt][q] = 0.f;

        for (int s = 0; s < 16; s++) {
            if (s >= 14) CP_COMMIT();     // empty groups so wait<2> forces chunk s
            cp_wait<2>();
            __syncthreads();

            if (s + 3 < 16) {
                uint32_t dst = sb + SM_A + ((s + 3) & 3) * 32768 + prec * 16384;
                const __half* src = hsrc + (s + 3) * 64;
#pragma unroll
                for (int i = 0; i < 8; i++)
                    cpa16(dst + SWZ128(rowoff + i * 16), src + i * 8);
                CP_COMMIT();
            }

            const uint32_t aHi = sb + SM_A + (s & 3) * 32768;
            const uint32_t aLo = aHi + 16384;
            const uint32_t wB  = sb + SM_W + (uint32_t)s * 4096;

#pragma unroll
            for (int kt = 0; kt < 4; kt++) {
                const uint32_t ka = (uint32_t)(kt * 32);
                uint32_t ah[4], alr[4];
                ldsm4(ah[0], ah[1], ah[2], ah[3],     aHi + aR + ((ka + akb) ^ aC));
                ldsm4(alr[0], alr[1], alr[2], alr[3], aLo + aR + ((ka + akb) ^ aC));
#pragma unroll
                for (int p = 0; p < 2; p++) {
                    uint32_t bh[4];
                    ldsm4(bh[0], bh[1], bh[2], bh[3], wB + bR[p] + ((ka + bkb) ^ bC[p]));
#pragma unroll
                    for (int h2 = 0; h2 < 2; h2++) {
                        float* d = acc[p * 2 + h2];
                        mma16816(d[0], d[1], d[2], d[3], ah[0], ah[1], ah[2], ah[3], bh[h2 * 2], bh[h2 * 2 + 1]);
                        mma16816(d[0], d[1], d[2], d[3], alr[0], alr[1], alr[2], alr[3], bh[h2 * 2], bh[h2 * 2 + 1]);
                    }
                }
            }
        }

        // register-local cell update: rows b0, b0+8; cols cta*8 + ec + {0,1}
#pragma unroll
        for (int h2 = 0; h2 < 2; h2++) {
            const int bb = b0 + h2 * 8;
            float hn[2];
            __half hh[2], hl[2];
#pragma unroll
            for (int q = 0; q < 2; q++) {
                float pi = acc[0][h2 * 2 + q] + (q ? gv[0][h2].y : gv[0][h2].x);
                float pf = acc[1][h2 * 2 + q] + (q ? gv[1][h2].y : gv[1][h2].x);
                float pg = acc[2][h2 * 2 + q] + (q ? gv[2][h2].y : gv[2][h2].x);
                float po = acc[3][h2 * 2 + q] + (q ? gv[3][h2].y : gv[3][h2].x);
                float iv = 1.f / (1.f + expf(-pi));
                float fv = 1.f / (1.f + expf(-pf));
                float gg = tanhf(pg);
                float ov = 1.f / (1.f + expf(-po));
                float cn = fv * creg[h2][q] + iv * gg;
                creg[h2][q] = cn;
                hn[q] = ov * tanhf(cn);
                hsplit(hn[q], hh[q], hl[q]);
            }
            long hb = (long)bb * HDIM + cta * 8 + ec;
            *(__half2*)&g_h_hi[nxt][hb] = *(__half2*)hh;
            *(__half2*)&g_h_lo[nxt][hb] = *(__half2*)hl;
            if (t == SLEN - 1) *(float2*)&g_h[hb] = make_float2(hn[0], hn[1]);
        }

        gridbar((unsigned)(t + 1));
    }
}

// ---------------------------------------------------------------------------
__global__ void k_fc(const float* __restrict__ fcW, const float* __restrict__ fcb,
                     float* __restrict__ out) {
    int b = blockIdx.x;
    int w = threadIdx.x >> 5, lane = threadIdx.x & 31;
    if (w >= ODIM) return;
    const float* hrow = g_h + b * HDIM;
    const float* wrow = fcW + w * HDIM;
    float s = 0.f;
    for (int k = lane; k < HDIM; k += 32) s += hrow[k] * wrow[k];
#pragma unroll
    for (int off = 16; off; off >>= 1) s += __shfl_xor_sync(0xffffffffu, s, off);
    if (lane == 0) out[b * ODIM + w] = s + fcb[w];
}

// ---------------------------------------------------------------------------
extern "C" void kernel_launch(void* const* d_in, const int* in_sizes, int n_in,
                              void* d_out, int out_size) {
    const void*  x   = d_in[0];
    const float* emb = (const float*)d_in[1];
    const float* Wii = (const float*)d_in[2];
    const float* bii = (const float*)d_in[3];
    const float* Whi = (const float*)d_in[4];
    const float* Wif = (const float*)d_in[5];
    const float* bif = (const float*)d_in[6];
    const float* Whf = (const float*)d_in[7];
    const float* Wig = (const float*)d_in[8];
    const float* big = (const float*)d_in[9];
    const float* Whg = (const float*)d_in[10];
    const float* Wio = (const float*)d_in[11];
    const float* bio = (const float*)d_in[12];
    const float* Who = (const float*)d_in[13];
    const float* fcW = (const float*)d_in[14];
    const float* fcb = (const float*)d_in[15];
    float* out = (float*)d_out;

    cudaFuncSetAttribute(k_step3, cudaFuncAttributeMaxDynamicSharedMemorySize,
                         SMEM_TC3);

    // launch order chosen so the persistent kernel is the 4th launch (ncu -s)
    k_prepA<<<MTOT + 512, 256>>>(x, emb);
    k_prepB<<<2 * NG, 256>>>(Wii, Wif, Wig, Wio, Whi, Whf, Whg, Who);
    k_igemm_tc<<<dim3(NG / 128, MTOT / 128), 256>>>(bii, bif, big, bio);
    k_step3<<<NCTA, NTH, SMEM_TC3>>>();
    k_fc<<<BD, 320>>>(fcW, fcb, out);
}

// round 8
// speedup vs baseline: 1.1744x; 1.0129x over previous
#include <cuda_runtime.h>
#include <cuda_fp16.h>
#include <math.h>
#include <stdint.h>

// Problem dims
#define BD    128
#define SLEN  256
#define EDIM  512
#define HDIM  1024
#define ODIM  10
#define NG    4096
#define MTOT  (BD*SLEN)

#define NCTA  128
#define NTH   512     // 16 warps: 2 K-groups x 8 M-warps

// ---------------------------------------------------------------------------
// Device scratch
// ---------------------------------------------------------------------------
// gatesx layout: [s][hb(128)][g(4)][b(128)][8]
__device__ float g_gatesx[(long)SLEN * BD * NG];
__device__ float g_h[BD * HDIM];

__device__ __half g_h_hi[2][BD * HDIM];
__device__ __half g_h_lo[2][BD * HDIM];
__device__ __half g_Whp[(long)NG * HDIM];   // fp16 W, n = cta*32 + g*8 + j
__device__ __half g_Wip[(long)NG * EDIM];   // fp16 W, n = g*1024 + col
__device__ __half g_e_hi[(long)MTOT * EDIM];
__device__ __half g_e_lo[(long)MTOT * EDIM];

__device__ unsigned          g_bar_cnt[8 * 64];
__device__ volatile unsigned g_bar_gen[8 * 64];

// ---------------------------------------------------------------------------
__device__ __forceinline__ void hsplit(float v, __half& hi, __half& lo) {
    hi = __float2half_rn(v);
    lo = __float2half_rn(v - __half2float(hi));
}

__device__ __forceinline__ void mma16816(float& d0, float& d1, float& d2, float& d3,
                                         uint32_t a0, uint32_t a1, uint32_t a2, uint32_t a3,
                                         uint32_t b0, uint32_t b1) {
    asm volatile("mma.sync.aligned.m16n8k16.row.col.f32.f16.f16.f32 "
                 "{%0,%1,%2,%3}, {%4,%5,%6,%7}, {%8,%9}, {%0,%1,%2,%3};"
                 : "+f"(d0), "+f"(d1), "+f"(d2), "+f"(d3)
                 : "r"(a0), "r"(a1), "r"(a2), "r"(a3), "r"(b0), "r"(b1));
}

__device__ __forceinline__ void ldsm4(uint32_t& r0, uint32_t& r1, uint32_t& r2,
                                      uint32_t& r3, uint32_t addr) {
    asm volatile("ldmatrix.sync.aligned.m8n8.x4.shared.b16 {%0,%1,%2,%3}, [%4];"
                 : "=r"(r0), "=r"(r1), "=r"(r2), "=r"(r3) : "r"(addr));
}

__device__ __forceinline__ void cpa16(uint32_t s, const void* g) {
    asm volatile("cp.async.cg.shared.global [%0], [%1], 16;\n" :: "r"(s), "l"(g));
}
#define CP_COMMIT() asm volatile("cp.async.commit_group;\n" ::: "memory")
template <int N> __device__ __forceinline__ void cp_wait() {
    asm volatile("cp.async.wait_group %0;\n" :: "n"(N) : "memory");
}
#define BARG(id) asm volatile("bar.sync %0, 256;" :: "r"(id) : "memory")

#define SWZ128(x) ((x) ^ (((x) >> 3) & 0x70))

// ---------------------------------------------------------------------------
// prepA: blocks [0, MTOT): embedding gather + fp16 split.
// Blocks [MTOT, MTOT+512): init h / barrier state.
// ---------------------------------------------------------------------------
__global__ void k_prepA(const void* __restrict__ xv, const float* __restrict__ emb) {
    const int blk = blockIdx.x;
    const int tid = threadIdx.x;
    if (blk < MTOT) {
        __shared__ int s64;
        if (tid == 0) {
            const int* xw = (const int*)xv;
            int zeros = 0;
            for (int i = 0; i < 64; i++)
                if (xw[2 * i + 1] == 0) zeros++;
            s64 = (zeros >= 60) ? 1 : 0;
        }
        __syncthreads();
        long tok = s64 ? (long)((const long long*)xv)[blk] : (long)((const int*)xv)[blk];
        const float* src = emb + tok * EDIM;
        for (int k = tid; k < EDIM; k += blockDim.x) {
            __half hi, lo;
            hsplit(src[k], hi, lo);
            g_e_hi[(long)blk * EDIM + k] = hi;
            g_e_lo[(long)blk * EDIM + k] = lo;
        }
    } else {
        int i = (blk - MTOT) * 256 + tid;
        if (i < BD * HDIM) {
            g_h_hi[0][i] = __float2half(0.f);
            g_h_lo[0][i] = __float2half(0.f);
        }
        if (i < 8 * 64) {
            g_bar_cnt[i] = 0u;
            g_bar_gen[i] = 0u;
        }
    }
}

// prepB: blocks [0, NG): pack input W (fp16). Blocks [NG, 2*NG): recurrent W.
__global__ void k_prepB(const float* __restrict__ Wii, const float* __restrict__ Wif,
                        const float* __restrict__ Wig, const float* __restrict__ Wio,
                        const float* __restrict__ Whi, const float* __restrict__ Whf,
                        const float* __restrict__ Whg, const float* __restrict__ Who) {
    const int blk = blockIdx.x;
    if (blk < NG) {
        int n = blk;
        int g = n >> 10, col = n & 1023;
        const float* src = ((g == 0) ? Wii : (g == 1) ? Wif : (g == 2) ? Wig : Wio)
                           + (long)col * EDIM;
        for (int k = threadIdx.x; k < EDIM; k += blockDim.x)
            g_Wip[(long)n * EDIM + k] = __float2half_rn(src[k]);
    } else {
        int n = blk - NG;
        int hb = n >> 5, r = n & 31, g = r >> 3, j = r & 7;
        int h = hb * 8 + j;
        const float* src = ((g == 0) ? Whi : (g == 1) ? Whf : (g == 2) ? Whg : Who)
                           + (long)h * HDIM;
        for (int k = threadIdx.x; k < HDIM; k += blockDim.x)
            g_Whp[(long)n * HDIM + k] = __float2half_rn(src[k]);
    }
}

// ---------------------------------------------------------------------------
// Input projection GEMM: [32768 x 512] @ [512 x 4096], fp16 2-term.
// ---------------------------------------------------------------------------
#define IP 24
__global__ __launch_bounds__(256)
void k_igemm_tc(const float* __restrict__ bi, const float* __restrict__ bf2,
                const float* __restrict__ bg, const float* __restrict__ bo) {
    __shared__ __align__(16) __half sm[2][3][128 * IP];

    const int tid = threadIdx.x;
    const int n0 = blockIdx.x * 128;
    const int M0 = blockIdx.y * 128;

    const int w = tid >> 5, lane = tid & 31;
    const int g = lane >> 2, tig = lane & 3;
    const int m0w = (w >> 1) * 32, n0w = (w & 1) * 64;

    const int sel0 = tid >> 7, idx0 = tid & 127;
    const __half* gp0 = (sel0 ? g_e_lo : g_e_hi) + (long)(M0 + idx0) * EDIM;
    const bool hasB = (tid < 128);
    const __half* gpB = g_Wip + (long)(n0 + tid) * EDIM;

    float acc[2][8][4];
#pragma unroll
    for (int mt = 0; mt < 2; mt++)
#pragma unroll
        for (int nt = 0; nt < 8; nt++)
#pragma unroll
            for (int q = 0; q < 4; q++) acc[mt][nt][q] = 0.f;

    uint4 p0[2], pB[2];
    p0[0] = ((const uint4*)gp0)[0]; p0[1] = ((const uint4*)gp0)[1];
    if (hasB) { pB[0] = ((const uint4*)gpB)[0]; pB[1] = ((const uint4*)gpB)[1]; }
    {
        uint4* d = (uint4*)(&sm[0][sel0][idx0 * IP]);
        d[0] = p0[0]; d[1] = p0[1];
        if (hasB) {
            uint4* d2 = (uint4*)(&sm[0][2][tid * IP]);
            d2[0] = pB[0]; d2[1] = pB[1];
        }
    }
    __syncthreads();

    const int NSTAGE = EDIM / 16;
    for (int s = 0; s < NSTAGE; s++) {
        int buf = s & 1;
        bool more = (s + 1 < NSTAGE);
        if (more) {
            gp0 += 16;
            p0[0] = ((const uint4*)gp0)[0]; p0[1] = ((const uint4*)gp0)[1];
            if (hasB) {
                gpB += 16;
                pB[0] = ((const uint4*)gpB)[0]; pB[1] = ((const uint4*)gpB)[1];
            }
        }
        const __half* Ah = sm[buf][0];
        const __half* Al = sm[buf][1];
        const __half* Bm = sm[buf][2];
        const int kb = 2 * tig;

        uint32_t aH[2][4], aL[2][4], bF[8][2];
#pragma unroll
        for (int mt = 0; mt < 2; mt++) {
            int rw = (m0w + mt * 16 + g) * IP + kb;
            aH[mt][0] = *(const uint32_t*)(Ah + rw);
            aH[mt][1] = *(const uint32_t*)(Ah + rw + 8 * IP);
            aH[mt][2] = *(const uint32_t*)(Ah + rw + 8);
            aH[mt][3] = *(const uint32_t*)(Ah + rw + 8 * IP + 8);
            aL[mt][0] = *(const uint32_t*)(Al + rw);
            aL[mt][1] = *(const uint32_t*)(Al + rw + 8 * IP);
            aL[mt][2] = *(const uint32_t*)(Al + rw + 8);
            aL[mt][3] = *(const uint32_t*)(Al + rw + 8 * IP + 8);
        }
#pragma unroll
        for (int nt = 0; nt < 8; nt++) {
            int cw = (n0w + nt * 8 + g) * IP + kb;
            bF[nt][0] = *(const uint32_t*)(Bm + cw);
            bF[nt][1] = *(const uint32_t*)(Bm + cw + 8);
        }
#pragma unroll
        for (int mt = 0; mt < 2; mt++)
#pragma unroll
            for (int nt = 0; nt < 8; nt++) {
                float* d = acc[mt][nt];
                mma16816(d[0], d[1], d[2], d[3], aH[mt][0], aH[mt][1], aH[mt][2], aH[mt][3], bF[nt][0], bF[nt][1]);
                mma16816(d[0], d[1], d[2], d[3], aL[mt][0], aL[mt][1], aL[mt][2], aL[mt][3], bF[nt][0], bF[nt][1]);
            }

        if (more) {
            uint4* d = (uint4*)(&sm[buf ^ 1][sel0][idx0 * IP]);
            d[0] = p0[0]; d[1] = p0[1];
            if (hasB) {
                uint4* d2 = (uint4*)(&sm[buf ^ 1][2][tid * IP]);
                d2[0] = pB[0]; d2[1] = pB[1];
            }
        }
        __syncthreads();
    }

#pragma unroll
    for (int mt = 0; mt < 2; mt++) {
        int r0 = m0w + mt * 16 + g;
#pragma unroll
        for (int nt = 0; nt < 8; nt++) {
            int col  = n0w + nt * 8 + 2 * tig;
            int ncol = n0 + col;
            int gate = ncol >> 10, hcol = ncol & 1023;
            int hb = hcol >> 3, j = hcol & 7;
            const float* bptr = (gate == 0) ? bi : (gate == 1) ? bf2 : (gate == 2) ? bg : bo;
            float bv0 = bptr[hcol], bv1 = bptr[hcol + 1];
#pragma unroll
            for (int hf = 0; hf < 2; hf++) {
                int mrow = M0 + r0 + hf * 8;
                int b = mrow >> 8, ss = mrow & 255;
                float2 v = make_float2(acc[mt][nt][hf * 2] + bv0, acc[mt][nt][hf * 2 + 1] + bv1);
                long off = ((((long)ss * 128 + hb) * 4 + gate) * 128 + b) * 8 + j;
                *(float2*)(g_gatesx + off) = v;
            }
        }
    }
}

// ---------------------------------------------------------------------------
// Persistent LSTM step kernel v4: split-K, 512 threads (16 warps).
// Group g2 = wid>>3 handles K[g2*512, g2*512+512). Warp wg = wid&7 owns
// M rows [wg*16, wg*16+16), all N=32. Group-local cp.async ring (kc=64,
// 2 bufs) + named barriers; group 1 partial sums reduced through SMEM;
// group 0 does the register-local cell update.
// ---------------------------------------------------------------------------
#define SM_A   0                       // 2 groups x 2 bufs x 32KB = 128KB
#define SM_W   131072                  // 64KB resident W
#define SM_R   (131072 + 65536)        // 16KB reduce
#define SMEM_TC4 (SM_R + 16384)        // 212992

__device__ __forceinline__ void gridbar(unsigned gen) {
    __syncthreads();
    if (threadIdx.x == 0) {
        __threadfence();
        int c = (blockIdx.x & 7) * 64;
        unsigned prev = atomicAdd(&g_bar_cnt[c], 1u);
        if (prev == (NCTA / 8) - 1) {
            g_bar_cnt[c] = 0u;
            __threadfence();
            g_bar_gen[c] = gen;
        }
    }
    if (threadIdx.x < 8) {
        while (g_bar_gen[threadIdx.x * 64] < gen) { }
        __threadfence();
    }
    __syncthreads();
}

__global__ __launch_bounds__(NTH, 1)
void k_step4() {
    extern __shared__ __align__(1024) unsigned char smraw[];
    const uint32_t sb = (uint32_t)__cvta_generic_to_shared(smraw);

    const int tid = threadIdx.x;
    const int cta = blockIdx.x;
    const int wid = tid >> 5, lane = tid & 31;
    const int g2 = wid >> 3;            // K-group
    const int wg = wid & 7;             // M-warp within group

    // ---- resident W (fp16, 32x1024) -> SMEM SW128 blocked-atom ----
    {
        const __half* wsrc = g_Whp + (long)cta * 32 * HDIM;
        unsigned char* wdst = smraw + SM_W;
        for (int idx = tid; idx < 32 * 128; idx += NTH) {
            int r = idx >> 7, cc = idx & 127;
            int c0 = cc * 8;
            uint32_t byte = (uint32_t)(((r >> 3) + (c0 >> 6) * 4) * 1024 + (r & 7) * 128 + (c0 & 63) * 2);
            *(uint4*)(wdst + SWZ128(byte)) = *(const uint4*)(wsrc + r * HDIM + c0);
        }
    }

    // ---- ldmatrix lane addresses ----
    const int aq = lane >> 3, al = lane & 7;
    const int am = wg * 16 + ((aq & 1) ? 8 : 0) + al;
    const uint32_t akb = (uint32_t)((aq >> 1) * 16);
    const uint32_t aR  = (uint32_t)((am >> 3) * 1024 + (am & 7) * 128);
    const uint32_t aC  = (uint32_t)((am & 7) * 16);
    const int bq = lane >> 3, bl = lane & 7;
    const int bn_off = (bq >> 1) * 8;
    const uint32_t bkb = (uint32_t)((bq & 1) * 16);
    uint32_t bR[2], bC[2];
#pragma unroll
    for (int p = 0; p < 2; p++) {
        int n = p * 16 + bn_off + bl;
        bR[p] = (uint32_t)((n >> 3) * 1024 + (n & 7) * 128);
        bC[p] = (uint32_t)((n & 7) * 16);
    }

    // loader mapping (per group): prec 0 hi / 1 lo, one h-row per thread
    const int ltid = tid & 255;
    const int prec = ltid >> 7;
    const int lrow = ltid & 127;
    const uint32_t rowoff = (uint32_t)((lrow >> 3) * 1024 + (lrow & 7) * 128);
    const uint32_t abase = sb + SM_A + (uint32_t)g2 * 65536;
    const int barid = 1 + g2;

    // epilogue mapping (group 0)
    const int er = lane >> 2, ec = (lane & 3) * 2;
    const int b0 = wg * 16 + er;
    const int ridx = wg * 32 + lane;
    float* sR = (float*)(smraw + SM_R);

    float creg[2][2];
    creg[0][0] = creg[0][1] = creg[1][0] = creg[1][1] = 0.f;

    __syncthreads();

    for (int t = 0; t < SLEN; t++) {
        const int par = t & 1, nxt = par ^ 1;
        const __half* hsrc = (prec ? g_h_lo[par] : g_h_hi[par])
                             + (long)lrow * HDIM + g2 * 512;

        // prologue: chunks 0,1 of this group's K-half
#pragma unroll
        for (int c = 0; c < 2; c++) {
            uint32_t dst = abase + (uint32_t)c * 32768 + (uint32_t)prec * 16384;
            const __half* src = hsrc + c * 64;
#pragma unroll
            for (int i = 0; i < 8; i++)
                cpa16(dst + SWZ128(rowoff + i * 16), src + i * 8);
            CP_COMMIT();
        }

        // gates preload into registers (group 0 only)
        float2 gv[4][2];
        if (g2 == 0) {
            const float* gx = g_gatesx + ((long)(t * 128 + cta) * 4) * 1024;
#pragma unroll
            for (int g = 0; g < 4; g++) {
                gv[g][0] = *(const float2*)(gx + (g * 128 + b0) * 8 + ec);
                gv[g][1] = *(const float2*)(gx + (g * 128 + b0 + 8) * 8 + ec);
            }
        }

        float acc[4][4];
#pragma unroll
        for (int nt = 0; nt < 4; nt++)
#pragma unroll
            for (int q = 0; q < 4; q++) acc[nt][q] = 0.f;

        for (int s = 0; s < 8; s++) {
            cp_wait<1>();
            BARG(barid);                       // chunk s visible group-wide

            const uint32_t aHi = abase + (uint32_t)(s & 1) * 32768;
            const uint32_t aLo = aHi + 16384;
            const uint32_t wB  = sb + SM_W + (uint32_t)(g2 * 8 + s) * 4096;

#pragma unroll
            for (int kt = 0; kt < 4; kt++) {
                const uint32_t ka = (uint32_t)(kt * 32);
                uint32_t ah[4], alr[4];
                ldsm4(ah[0], ah[1], ah[2], ah[3],     aHi + aR + ((ka + akb) ^ aC));
                ldsm4(alr[0], alr[1], alr[2], alr[3], aLo + aR + ((ka + akb) ^ aC));
#pragma unroll
                for (int p = 0; p < 2; p++) {
                    uint32_t bh[4];
                    ldsm4(bh[0], bh[1], bh[2], bh[3], wB + bR[p] + ((ka + bkb) ^ bC[p]));
#pragma unroll
                    for (int h2 = 0; h2 < 2; h2++) {
                        float* d = acc[p * 2 + h2];
                        mma16816(d[0], d[1], d[2], d[3], ah[0], ah[1], ah[2], ah[3], bh[h2 * 2], bh[h2 * 2 + 1]);
                        mma16816(d[0], d[1], d[2], d[3], alr[0], alr[1], alr[2], alr[3], bh[h2 * 2], bh[h2 * 2 + 1]);
                    }
                }
            }

            BARG(barid);                       // all reads of buf (s&1) done
            if (s + 2 < 8) {
                uint32_t dst = abase + (uint32_t)(s & 1) * 32768 + (uint32_t)prec * 16384;
                const __half* src = hsrc + (s + 2) * 64;
#pragma unroll
                for (int i = 0; i < 8; i++)
                    cpa16(dst + SWZ128(rowoff + i * 16), src + i * 8);
            }
            CP_COMMIT();
        }

        // reduce: group 1 -> SMEM
        if (g2 == 1) {
#pragma unroll
            for (int q = 0; q < 16; q++)
                sR[q * 256 + ridx] = acc[q >> 2][q & 3];
        }
        __syncthreads();

        if (g2 == 0) {
#pragma unroll
            for (int q = 0; q < 16; q++)
                acc[q >> 2][q & 3] += sR[q * 256 + ridx];

            // register-local cell update: rows b0, b0+8; cols cta*8+ec+{0,1}
#pragma unroll
            for (int h2 = 0; h2 < 2; h2++) {
                const int bb = b0 + h2 * 8;
                float hn[2];
                __half hh[2], hl[2];
#pragma unroll
                for (int q = 0; q < 2; q++) {
                    float pi = acc[0][h2 * 2 + q] + (q ? gv[0][h2].y : gv[0][h2].x);
                    float pf = acc[1][h2 * 2 + q] + (q ? gv[1][h2].y : gv[1][h2].x);
                    float pg = acc[2][h2 * 2 + q] + (q ? gv[2][h2].y : gv[2][h2].x);
                    float po = acc[3][h2 * 2 + q] + (q ? gv[3][h2].y : gv[3][h2].x);
                    float iv = 1.f / (1.f + expf(-pi));
                    float fv = 1.f / (1.f + expf(-pf));
                    float gg = tanhf(pg);
                    float ov = 1.f / (1.f + expf(-po));
                    float cn = fv * creg[h2][q] + iv * gg;
                    creg[h2][q] = cn;
                    hn[q] = ov * tanhf(cn);
                    hsplit(hn[q], hh[q], hl[q]);
                }
                long hb = (long)bb * HDIM + cta * 8 + ec;
                *(__half2*)&g_h_hi[nxt][hb] = *(__half2*)hh;
                *(__half2*)&g_h_lo[nxt][hb] = *(__half2*)hl;
                if (t == SLEN - 1) *(float2*)&g_h[hb] = make_float2(hn[0], hn[1]);
            }
        }

        gridbar((unsigned)(t + 1));
    }
}

// ---------------------------------------------------------------------------
__global__ void k_fc(const float* __restrict__ fcW, const float* __restrict__ fcb,
                     float* __restrict__ out) {
    int b = blockIdx.x;
    int w = threadIdx.x >> 5, lane = threadIdx.x & 31;
    if (w >= ODIM) return;
    const float* hrow = g_h + b * HDIM;
    const float* wrow = fcW + w * HDIM;
    float s = 0.f;
    for (int k = lane; k < HDIM; k += 32) s += hrow[k] * wrow[k];
#pragma unroll
    for (int off = 16; off; off >>= 1) s += __shfl_xor_sync(0xffffffffu, s, off);
    if (lane == 0) out[b * ODIM + w] = s + fcb[w];
}

// ---------------------------------------------------------------------------
extern "C" void kernel_launch(void* const* d_in, const int* in_sizes, int n_in,
                              void* d_out, int out_size) {
    const void*  x   = d_in[0];
    const float* emb = (const float*)d_in[1];
    const float* Wii = (const float*)d_in[2];
    const float* bii = (const float*)d_in[3];
    const float* Whi = (const float*)d_in[4];
    const float* Wif = (const float*)d_in[5];
    const float* bif = (const float*)d_in[6];
    const float* Whf = (const float*)d_in[7];
    const float* Wig = (const float*)d_in[8];
    const float* big = (const float*)d_in[9];
    const float* Whg = (const float*)d_in[10];
    const float* Wio = (const float*)d_in[11];
    const float* bio = (const float*)d_in[12];
    const float* Who = (const float*)d_in[13];
    const float* fcW = (const float*)d_in[14];
    const float* fcb = (const float*)d_in[15];
    float* out = (float*)d_out;

    cudaFuncSetAttribute(k_step4, cudaFuncAttributeMaxDynamicSharedMemorySize,
                         SMEM_TC4);

    k_prepA<<<MTOT + 512, 256>>>(x, emb);
    k_prepB<<<2 * NG, 256>>>(Wii, Wif, Wig, Wio, Whi, Whf, Whg, Who);
    k_igemm_tc<<<dim3(NG / 128, MTOT / 128), 256>>>(bii, bif, big, bio);
    k_step4<<<NCTA, NTH, SMEM_TC4>>>();
    k_fc<<<BD, 320>>>(fcW, fcb, out);
}

// round 9
// speedup vs baseline: 2.2819x; 1.9431x over previous
#include <cuda_runtime.h>
#include <cuda_fp16.h>
#include <math.h>
#include <stdint.h>

// Problem dims
#define BD    128
#define SLEN  256
#define EDIM  512
#define HDIM  1024
#define ODIM  10
#define NG    4096
#define MTOT  (BD*SLEN)

#define NCTA  128
#define NTH   512     // 16 warps: 2 K-groups x 8 M-warps

// ---------------------------------------------------------------------------
// Device scratch
// ---------------------------------------------------------------------------
// gatesx layout: [s][hb(128)][g(4)][b(128)][8]
__device__ float g_gatesx[(long)SLEN * BD * NG];
__device__ float g_h[BD * HDIM];

__device__ __half g_h_hi[2][BD * HDIM];
__device__ __half g_h_lo[2][BD * HDIM];
__device__ __half g_Whp[(long)NG * HDIM];   // fp16 W, n = cta*32 + g*8 + j
__device__ __half g_Wip[(long)NG * EDIM];   // fp16 W, n = g*1024 + col
__device__ __half g_e_hi[(long)MTOT * EDIM];
__device__ __half g_e_lo[(long)MTOT * EDIM];

__device__ unsigned          g_bar_cnt[8 * 64];
__device__ volatile unsigned g_bar_gen[8 * 64];

// ---------------------------------------------------------------------------
__device__ __forceinline__ void hsplit(float v, __half& hi, __half& lo) {
    hi = __float2half_rn(v);
    lo = __float2half_rn(v - __half2float(hi));
}

__device__ __forceinline__ void mma16816(float& d0, float& d1, float& d2, float& d3,
                                         uint32_t a0, uint32_t a1, uint32_t a2, uint32_t a3,
                                         uint32_t b0, uint32_t b1) {
    asm volatile("mma.sync.aligned.m16n8k16.row.col.f32.f16.f16.f32 "
                 "{%0,%1,%2,%3}, {%4,%5,%6,%7}, {%8,%9}, {%0,%1,%2,%3};"
                 : "+f"(d0), "+f"(d1), "+f"(d2), "+f"(d3)
                 : "r"(a0), "r"(a1), "r"(a2), "r"(a3), "r"(b0), "r"(b1));
}

__device__ __forceinline__ void ldsm4(uint32_t& r0, uint32_t& r1, uint32_t& r2,
                                      uint32_t& r3, uint32_t addr) {
    asm volatile("ldmatrix.sync.aligned.m8n8.x4.shared.b16 {%0,%1,%2,%3}, [%4];"
                 : "=r"(r0), "=r"(r1), "=r"(r2), "=r"(r3) : "r"(addr));
}

__device__ __forceinline__ void cpa16(uint32_t s, const void* g) {
    asm volatile("cp.async.cg.shared.global [%0], [%1], 16;\n" :: "r"(s), "l"(g));
}
#define CP_COMMIT() asm volatile("cp.async.commit_group;\n" ::: "memory")
template <int N> __device__ __forceinline__ void cp_wait() {
    asm volatile("cp.async.wait_group %0;\n" :: "n"(N) : "memory");
}
#define BARG(id) asm volatile("bar.sync %0, 256;" :: "r"(id) : "memory")

#define SWZ128(x) ((x) ^ (((x) >> 3) & 0x70))

// ---------------------------------------------------------------------------
// prepA: blocks [0, MTOT): embedding gather + fp16 split.
// Blocks [MTOT, MTOT+512): init h / barrier state.
// ---------------------------------------------------------------------------
__global__ void k_prepA(const void* __restrict__ xv, const float* __restrict__ emb) {
    const int blk = blockIdx.x;
    const int tid = threadIdx.x;
    if (blk < MTOT) {
        __shared__ int s64;
        if (tid == 0) {
            const int* xw = (const int*)xv;
            int zeros = 0;
            for (int i = 0; i < 64; i++)
                if (xw[2 * i + 1] == 0) zeros++;
            s64 = (zeros >= 60) ? 1 : 0;
        }
        __syncthreads();
        long tok = s64 ? (long)((const long long*)xv)[blk] : (long)((const int*)xv)[blk];
        const float* src = emb + tok * EDIM;
        for (int k = tid; k < EDIM; k += blockDim.x) {
            __half hi, lo;
            hsplit(src[k], hi, lo);
            g_e_hi[(long)blk * EDIM + k] = hi;
            g_e_lo[(long)blk * EDIM + k] = lo;
        }
    } else {
        int i = (blk - MTOT) * 256 + tid;
        if (i < BD * HDIM) {
            g_h_hi[0][i] = __float2half(0.f);
            g_h_lo[0][i] = __float2half(0.f);
        }
        if (i < 8 * 64) {
            g_bar_cnt[i] = 0u;
            g_bar_gen[i] = 0u;
        }
    }
}

// prepB: blocks [0, NG): pack input W (fp16). Blocks [NG, 2*NG): recurrent W.
__global__ void k_prepB(const float* __restrict__ Wii, const float* __restrict__ Wif,
                        const float* __restrict__ Wig, const float* __restrict__ Wio,
                        const float* __restrict__ Whi, const float* __restrict__ Whf,
                        const float* __restrict__ Whg, const float* __restrict__ Who) {
    const int blk = blockIdx.x;
    if (blk < NG) {
        int n = blk;
        int g = n >> 10, col = n & 1023;
        const float* src = ((g == 0) ? Wii : (g == 1) ? Wif : (g == 2) ? Wig : Wio)
                           + (long)col * EDIM;
        for (int k = threadIdx.x; k < EDIM; k += blockDim.x)
            g_Wip[(long)n * EDIM + k] = __float2half_rn(src[k]);
    } else {
        int n = blk - NG;
        int hb = n >> 5, r = n & 31, g = r >> 3, j = r & 7;
        int h = hb * 8 + j;
        const float* src = ((g == 0) ? Whi : (g == 1) ? Whf : (g == 2) ? Whg : Who)
                           + (long)h * HDIM;
        for (int k = threadIdx.x; k < HDIM; k += blockDim.x)
            g_Whp[(long)n * HDIM + k] = __float2half_rn(src[k]);
    }
}

// ---------------------------------------------------------------------------
// Input projection GEMM: [32768 x 512] @ [512 x 4096], fp16 2-term.
// ---------------------------------------------------------------------------
#define IP 24
__global__ __launch_bounds__(256)
void k_igemm_tc(const float* __restrict__ bi, const float* __restrict__ bf2,
                const float* __restrict__ bg, const float* __restrict__ bo) {
    __shared__ __align__(16) __half sm[2][3][128 * IP];

    const int tid = threadIdx.x;
    const int n0 = blockIdx.x * 128;
    const int M0 = blockIdx.y * 128;

    const int w = tid >> 5, lane = tid & 31;
    const int g = lane >> 2, tig = lane & 3;
    const int m0w = (w >> 1) * 32, n0w = (w & 1) * 64;

    const int sel0 = tid >> 7, idx0 = tid & 127;
    const __half* gp0 = (sel0 ? g_e_lo : g_e_hi) + (long)(M0 + idx0) * EDIM;
    const bool hasB = (tid < 128);
    const __half* gpB = g_Wip + (long)(n0 + tid) * EDIM;

    float acc[2][8][4];
#pragma unroll
    for (int mt = 0; mt < 2; mt++)
#pragma unroll
        for (int nt = 0; nt < 8; nt++)
#pragma unroll
            for (int q = 0; q < 4; q++) acc[mt][nt][q] = 0.f;

    uint4 p0[2], pB[2];
    p0[0] = ((const uint4*)gp0)[0]; p0[1] = ((const uint4*)gp0)[1];
    if (hasB) { pB[0] = ((const uint4*)gpB)[0]; pB[1] = ((const uint4*)gpB)[1]; }
    {
        uint4* d = (uint4*)(&sm[0][sel0][idx0 * IP]);
        d[0] = p0[0]; d[1] = p0[1];
        if (hasB) {
            uint4* d2 = (uint4*)(&sm[0][2][tid * IP]);
            d2[0] = pB[0]; d2[1] = pB[1];
        }
    }
    __syncthreads();

    const int NSTAGE = EDIM / 16;
    for (int s = 0; s < NSTAGE; s++) {
        int buf = s & 1;
        bool more = (s + 1 < NSTAGE);
        if (more) {
            gp0 += 16;
            p0[0] = ((const uint4*)gp0)[0]; p0[1] = ((const uint4*)gp0)[1];
            if (hasB) {
                gpB += 16;
                pB[0] = ((const uint4*)gpB)[0]; pB[1] = ((const uint4*)gpB)[1];
            }
        }
        const __half* Ah = sm[buf][0];
        const __half* Al = sm[buf][1];
        const __half* Bm = sm[buf][2];
        const int kb = 2 * tig;

        uint32_t aH[2][4], aL[2][4], bF[8][2];
#pragma unroll
        for (int mt = 0; mt < 2; mt++) {
            int rw = (m0w + mt * 16 + g) * IP + kb;
            aH[mt][0] = *(const uint32_t*)(Ah + rw);
            aH[mt][1] = *(const uint32_t*)(Ah + rw + 8 * IP);
            aH[mt][2] = *(const uint32_t*)(Ah + rw + 8);
            aH[mt][3] = *(const uint32_t*)(Ah + rw + 8 * IP + 8);
            aL[mt][0] = *(const uint32_t*)(Al + rw);
            aL[mt][1] = *(const uint32_t*)(Al + rw + 8 * IP);
            aL[mt][2] = *(const uint32_t*)(Al + rw + 8);
            aL[mt][3] = *(const uint32_t*)(Al + rw + 8 * IP + 8);
        }
#pragma unroll
        for (int nt = 0; nt < 8; nt++) {
            int cw = (n0w + nt * 8 + g) * IP + kb;
            bF[nt][0] = *(const uint32_t*)(Bm + cw);
            bF[nt][1] = *(const uint32_t*)(Bm + cw + 8);
        }
#pragma unroll
        for (int mt = 0; mt < 2; mt++)
#pragma unroll
            for (int nt = 0; nt < 8; nt++) {
                float* d = acc[mt][nt];
                mma16816(d[0], d[1], d[2], d[3], aH[mt][0], aH[mt][1], aH[mt][2], aH[mt][3], bF[nt][0], bF[nt][1]);
                mma16816(d[0], d[1], d[2], d[3], aL[mt][0], aL[mt][1], aL[mt][2], aL[mt][3], bF[nt][0], bF[nt][1]);
            }

        if (more) {
            uint4* d = (uint4*)(&sm[buf ^ 1][sel0][idx0 * IP]);
            d[0] = p0[0]; d[1] = p0[1];
            if (hasB) {
                uint4* d2 = (uint4*)(&sm[buf ^ 1][2][tid * IP]);
                d2[0] = pB[0]; d2[1] = pB[1];
            }
        }
        __syncthreads();
    }

#pragma unroll
    for (int mt = 0; mt < 2; mt++) {
        int r0 = m0w + mt * 16 + g;
#pragma unroll
        for (int nt = 0; nt < 8; nt++) {
            int col  = n0w + nt * 8 + 2 * tig;
            int ncol = n0 + col;
            int gate = ncol >> 10, hcol = ncol & 1023;
            int hb = hcol >> 3, j = hcol & 7;
            const float* bptr = (gate == 0) ? bi : (gate == 1) ? bf2 : (gate == 2) ? bg : bo;
            float bv0 = bptr[hcol], bv1 = bptr[hcol + 1];
#pragma unroll
            for (int hf = 0; hf < 2; hf++) {
                int mrow = M0 + r0 + hf * 8;
                int b = mrow >> 8, ss = mrow & 255;
                float2 v = make_float2(acc[mt][nt][hf * 2] + bv0, acc[mt][nt][hf * 2 + 1] + bv1);
                long off = ((((long)ss * 128 + hb) * 4 + gate) * 128 + b) * 8 + j;
                *(float2*)(g_gatesx + off) = v;
            }
        }
    }
}

// ---------------------------------------------------------------------------
// Persistent LSTM step kernel v5: split-K, 512 threads, COALESCED h loader.
// Loader: warp-instr lanes cover 4 rows x 8 consecutive 16B segs = 4 full
// 128B lines (4 L1tex wavefronts/instr instead of 32).
// ---------------------------------------------------------------------------
#define SM_A   0                       // 2 groups x 2 bufs x 32KB = 128KB
#define SM_W   131072                  // 64KB resident W
#define SM_R   (131072 + 65536)        // 16KB reduce
#define SMEM_TC5 (SM_R + 16384)        // 212992

__device__ __forceinline__ void gridbar(unsigned gen) {
    __syncthreads();
    if (threadIdx.x == 0) {
        __threadfence();
        int c = (blockIdx.x & 7) * 64;
        unsigned prev = atomicAdd(&g_bar_cnt[c], 1u);
        if (prev == (NCTA / 8) - 1) {
            g_bar_cnt[c] = 0u;
            __threadfence();
            g_bar_gen[c] = gen;
        }
    }
    if (threadIdx.x < 8) {
        while (g_bar_gen[threadIdx.x * 64] < gen) { }
        __threadfence();
    }
    __syncthreads();
}

__global__ __launch_bounds__(NTH, 1)
void k_step5() {
    extern __shared__ __align__(1024) unsigned char smraw[];
    const uint32_t sb = (uint32_t)__cvta_generic_to_shared(smraw);

    const int tid = threadIdx.x;
    const int cta = blockIdx.x;
    const int wid = tid >> 5, lane = tid & 31;
    const int g2 = wid >> 3;            // K-group
    const int wg = wid & 7;             // M-warp within group

    // ---- resident W (fp16, 32x1024) -> SMEM SW128 blocked-atom ----
    {
        const __half* wsrc = g_Whp + (long)cta * 32 * HDIM;
        unsigned char* wdst = smraw + SM_W;
        for (int idx = tid; idx < 32 * 128; idx += NTH) {
            int r = idx >> 7, cc = idx & 127;
            int c0 = cc * 8;
            uint32_t byte = (uint32_t)(((r >> 3) + (c0 >> 6) * 4) * 1024 + (r & 7) * 128 + (c0 & 63) * 2);
            *(uint4*)(wdst + SWZ128(byte)) = *(const uint4*)(wsrc + r * HDIM + c0);
        }
    }

    // ---- ldmatrix lane addresses ----
    const int aq = lane >> 3, al = lane & 7;
    const int am = wg * 16 + ((aq & 1) ? 8 : 0) + al;
    const uint32_t akb = (uint32_t)((aq >> 1) * 16);
    const uint32_t aR  = (uint32_t)((am >> 3) * 1024 + (am & 7) * 128);
    const uint32_t aC  = (uint32_t)((am & 7) * 16);
    const int bq = lane >> 3, bl = lane & 7;
    const int bn_off = (bq >> 1) * 8;
    const uint32_t bkb = (uint32_t)((bq & 1) * 16);
    uint32_t bR[2], bC[2];
#pragma unroll
    for (int p = 0; p < 2; p++) {
        int n = p * 16 + bn_off + bl;
        bR[p] = (uint32_t)((n >> 3) * 1024 + (n & 7) * 128);
        bC[p] = (uint32_t)((n & 7) * 16);
    }

    // ---- coalesced loader mapping (per group) ----
    // ltid: seg = ltid&7 (16B seg of 128B row-chunk), slot = ltid>>3 (0..31).
    // Thread loads rows {slot, slot+32, slot+64, slot+96} for prec=0 (i=0..3)
    // and the same rows for prec=1 (i=4..7). Warp-instr = 4 rows x 8 segs
    // = 4 full 128B lines.
    const int seg  = tid & 7;
    const int slot = (tid >> 3) & 31;
    const uint32_t dst0 = (uint32_t)((slot >> 3) * 1024 + (slot & 7) * 128 + seg * 16);
    const uint32_t abase = sb + SM_A + (uint32_t)g2 * 65536;
    const int barid = 1 + g2;

    // epilogue mapping (group 0)
    const int er = lane >> 2, ec = (lane & 3) * 2;
    const int b0 = wg * 16 + er;
    const int ridx = wg * 32 + lane;
    float* sR = (float*)(smraw + SM_R);

    float creg[2][2];
    creg[0][0] = creg[0][1] = creg[1][0] = creg[1][1] = 0.f;

    __syncthreads();

    for (int t = 0; t < SLEN; t++) {
        const int par = t & 1, nxt = par ^ 1;
        // src base for this thread: row=slot (+32i), K-col = g2*512 + s*64 + seg*8
        const __half* srcH = g_h_hi[par] + (long)slot * HDIM + g2 * 512 + seg * 8;
        const __half* srcL = g_h_lo[par] + (long)slot * HDIM + g2 * 512 + seg * 8;

        // prologue: chunks 0,1 of this group's K-half
#pragma unroll
        for (int c = 0; c < 2; c++) {
            uint32_t dst = abase + (uint32_t)c * 32768;
            const __half* sH = srcH + c * 64;
            const __half* sL = srcL + c * 64;
#pragma unroll
            for (int i = 0; i < 4; i++) {
                cpa16(dst + SWZ128(dst0 + i * 4096),         sH + i * 32 * HDIM);
                cpa16(dst + 16384 + SWZ128(dst0 + i * 4096), sL + i * 32 * HDIM);
            }
            CP_COMMIT();
        }

        // gates preload into registers (group 0 only)
        float2 gv[4][2];
        if (g2 == 0) {
            const float* gx = g_gatesx + ((long)(t * 128 + cta) * 4) * 1024;
#pragma unroll
            for (int g = 0; g < 4; g++) {
                gv[g][0] = *(const float2*)(gx + (g * 128 + b0) * 8 + ec);
                gv[g][1] = *(const float2*)(gx + (g * 128 + b0 + 8) * 8 + ec);
            }
        }

        float acc[4][4];
#pragma unroll
        for (int nt = 0; nt < 4; nt++)
#pragma unroll
            for (int q = 0; q < 4; q++) acc[nt][q] = 0.f;

        for (int s = 0; s < 8; s++) {
            cp_wait<1>();
            BARG(barid);                       // chunk s visible group-wide

            const uint32_t aHi = abase + (uint32_t)(s & 1) * 32768;
            const uint32_t aLo = aHi + 16384;
            const uint32_t wB  = sb + SM_W + (uint32_t)(g2 * 8 + s) * 4096;

#pragma unroll
            for (int kt = 0; kt < 4; kt++) {
                const uint32_t ka = (uint32_t)(kt * 32);
                uint32_t ah[4], alr[4];
                ldsm4(ah[0], ah[1], ah[2], ah[3],     aHi + aR + ((ka + akb) ^ aC));
                ldsm4(alr[0], alr[1], alr[2], alr[3], aLo + aR + ((ka + akb) ^ aC));
#pragma unroll
                for (int p = 0; p < 2; p++) {
                    uint32_t bh[4];
                    ldsm4(bh[0], bh[1], bh[2], bh[3], wB + bR[p] + ((ka + bkb) ^ bC[p]));
#pragma unroll
                    for (int h2 = 0; h2 < 2; h2++) {
                        float* d = acc[p * 2 + h2];
                        mma16816(d[0], d[1], d[2], d[3], ah[0], ah[1], ah[2], ah[3], bh[h2 * 2], bh[h2 * 2 + 1]);
                        mma16816(d[0], d[1], d[2], d[3], alr[0], alr[1], alr[2], alr[3], bh[h2 * 2], bh[h2 * 2 + 1]);
                    }
                }
            }

            BARG(barid);                       // all reads of buf (s&1) done
            if (s + 2 < 8) {
                uint32_t dst = abase + (uint32_t)(s & 1) * 32768;
                const __half* sH = srcH + (s + 2) * 64;
                const __half* sL = srcL + (s + 2) * 64;
#pragma unroll
                for (int i = 0; i < 4; i++) {
                    cpa16(dst + SWZ128(dst0 + i * 4096),         sH + i * 32 * HDIM);
                    cpa16(dst + 16384 + SWZ128(dst0 + i * 4096), sL + i * 32 * HDIM);
                }
            }
            CP_COMMIT();
        }

        // reduce: group 1 -> SMEM
        if (g2 == 1) {
#pragma unroll
            for (int q = 0; q < 16; q++)
                sR[q * 256 + ridx] = acc[q >> 2][q & 3];
        }
        __syncthreads();

        if (g2 == 0) {
#pragma unroll
            for (int q = 0; q < 16; q++)
                acc[q >> 2][q & 3] += sR[q * 256 + ridx];

            // register-local cell update: rows b0, b0+8; cols cta*8+ec+{0,1}
#pragma unroll
            for (int h2 = 0; h2 < 2; h2++) {
                const int bb = b0 + h2 * 8;
                float hn[2];
                __half hh[2], hl[2];
#pragma unroll
                for (int q = 0; q < 2; q++) {
                    float pi = acc[0][h2 * 2 + q] + (q ? gv[0][h2].y : gv[0][h2].x);
                    float pf = acc[1][h2 * 2 + q] + (q ? gv[1][h2].y : gv[1][h2].x);
                    float pg = acc[2][h2 * 2 + q] + (q ? gv[2][h2].y : gv[2][h2].x);
                    float po = acc[3][h2 * 2 + q] + (q ? gv[3][h2].y : gv[3][h2].x);
                    float iv = 1.f / (1.f + expf(-pi));
                    float fv = 1.f / (1.f + expf(-pf));
                    float gg = tanhf(pg);
                    float ov = 1.f / (1.f + expf(-po));
                    float cn = fv * creg[h2][q] + iv * gg;
                    creg[h2][q] = cn;
                    hn[q] = ov * tanhf(cn);
                    hsplit(hn[q], hh[q], hl[q]);
                }
                long hb = (long)bb * HDIM + cta * 8 + ec;
                *(__half2*)&g_h_hi[nxt][hb] = *(__half2*)hh;
                *(__half2*)&g_h_lo[nxt][hb] = *(__half2*)hl;
                if (t == SLEN - 1) *(float2*)&g_h[hb] = make_float2(hn[0], hn[1]);
            }
        }

        gridbar((unsigned)(t + 1));
    }
}

// ---------------------------------------------------------------------------
__global__ void k_fc(const float* __restrict__ fcW, const float* __restrict__ fcb,
                     float* __restrict__ out) {
    int b = blockIdx.x;
    int w = threadIdx.x >> 5, lane = threadIdx.x & 31;
    if (w >= ODIM) return;
    const float* hrow = g_h + b * HDIM;
    const float* wrow = fcW + w * HDIM;
    float s = 0.f;
    for (int k = lane; k < HDIM; k += 32) s += hrow[k] * wrow[k];
#pragma unroll
    for (int off = 16; off; off >>= 1) s += __shfl_xor_sync(0xffffffffu, s, off);
    if (lane == 0) out[b * ODIM + w] = s + fcb[w];
}

// ---------------------------------------------------------------------------
extern "C" void kernel_launch(void* const* d_in, const int* in_sizes, int n_in,
                              void* d_out, int out_size) {
    const void*  x   = d_in[0];
    const float* emb = (const float*)d_in[1];
    const float* Wii = (const float*)d_in[2];
    const float* bii = (const float*)d_in[3];
    const float* Whi = (const float*)d_in[4];
    const float* Wif = (const float*)d_in[5];
    const float* bif = (const float*)d_in[6];
    const float* Whf = (const float*)d_in[7];
    const float* Wig = (const float*)d_in[8];
    const float* big = (const float*)d_in[9];
    const float* Whg = (const float*)d_in[10];
    const float* Wio = (const float*)d_in[11];
    const float* bio = (const float*)d_in[12];
    const float* Who = (const float*)d_in[13];
    const float* fcW = (const float*)d_in[14];
    const float* fcb = (const float*)d_in[15];
    float* out = (float*)d_out;

    cudaFuncSetAttribute(k_step5, cudaFuncAttributeMaxDynamicSharedMemorySize,
                         SMEM_TC5);

    k_prepA<<<MTOT + 512, 256>>>(x, emb);
    k_prepB<<<2 * NG, 256>>>(Wii, Wif, Wig, Wio, Whi, Whf, Whg, Who);
    k_igemm_tc<<<dim3(NG / 128, MTOT / 128), 256>>>(bii, bif, big, bio);
    k_step5<<<NCTA, NTH, SMEM_TC5>>>();
    k_fc<<<BD, 320>>>(fcW, fcb, out);
}

// round 10
// speedup vs baseline: 2.9724x; 1.3026x over previous
#include <cuda_runtime.h>
#include <cuda_fp16.h>
#include <math.h>
#include <stdint.h>

// Problem dims
#define BD    128
#define SLEN  256
#define EDIM  512
#define HDIM  1024
#define ODIM  10
#define NG    4096
#define MTOT  (BD*SLEN)

#define NCTA  128
#define NTH   512     // 16 warps: 2 K-groups x 8 M-warps

// ---------------------------------------------------------------------------
// Device scratch
// ---------------------------------------------------------------------------
// gatesx layout: [s][hb(128)][g(4)][b(128)][8]
__device__ float g_gatesx[(long)SLEN * BD * NG];
__device__ float g_h[BD * HDIM];

__device__ __half g_h16[2][BD * HDIM];      // fp16 h, ping-pong
__device__ __half g_Whp[(long)NG * HDIM];   // fp16 W, n = cta*32 + g*8 + j
__device__ __half g_Wip[(long)NG * EDIM];   // fp16 W, n = g*1024 + col
__device__ __half g_e16[(long)MTOT * EDIM]; // fp16 gathered embeddings

__device__ unsigned          g_bar_cnt[8 * 64];
__device__ volatile unsigned g_bar_gen[8 * 64];

// ---------------------------------------------------------------------------
__device__ __forceinline__ void mma16816(float& d0, float& d1, float& d2, float& d3,
                                         uint32_t a0, uint32_t a1, uint32_t a2, uint32_t a3,
                                         uint32_t b0, uint32_t b1) {
    asm volatile("mma.sync.aligned.m16n8k16.row.col.f32.f16.f16.f32 "
                 "{%0,%1,%2,%3}, {%4,%5,%6,%7}, {%8,%9}, {%0,%1,%2,%3};"
                 : "+f"(d0), "+f"(d1), "+f"(d2), "+f"(d3)
                 : "r"(a0), "r"(a1), "r"(a2), "r"(a3), "r"(b0), "r"(b1));
}

__device__ __forceinline__ void ldsm4(uint32_t& r0, uint32_t& r1, uint32_t& r2,
                                      uint32_t& r3, uint32_t addr) {
    asm volatile("ldmatrix.sync.aligned.m8n8.x4.shared.b16 {%0,%1,%2,%3}, [%4];"
                 : "=r"(r0), "=r"(r1), "=r"(r2), "=r"(r3) : "r"(addr));
}

__device__ __forceinline__ void cpa16(uint32_t s, const void* g) {
    asm volatile("cp.async.cg.shared.global [%0], [%1], 16;\n" :: "r"(s), "l"(g));
}
#define CP_COMMIT() asm volatile("cp.async.commit_group;\n" ::: "memory")
template <int N> __device__ __forceinline__ void cp_wait() {
    asm volatile("cp.async.wait_group %0;\n" :: "n"(N) : "memory");
}
#define BARG(id) asm volatile("bar.sync %0, 256;" :: "r"(id) : "memory")

#define SWZ128(x) ((x) ^ (((x) >> 3) & 0x70))

// ---------------------------------------------------------------------------
// prepA: blocks [0, MTOT): embedding gather + fp16 round.
// Blocks [MTOT, MTOT+512): init h / barrier state.
// ---------------------------------------------------------------------------
__global__ void k_prepA(const void* __restrict__ xv, const float* __restrict__ emb) {
    const int blk = blockIdx.x;
    const int tid = threadIdx.x;
    if (blk < MTOT) {
        __shared__ int s64;
        if (tid == 0) {
            const int* xw = (const int*)xv;
            int zeros = 0;
            for (int i = 0; i < 64; i++)
                if (xw[2 * i + 1] == 0) zeros++;
            s64 = (zeros >= 60) ? 1 : 0;
        }
        __syncthreads();
        long tok = s64 ? (long)((const long long*)xv)[blk] : (long)((const int*)xv)[blk];
        const float* src = emb + tok * EDIM;
        for (int k = tid; k < EDIM; k += blockDim.x)
            g_e16[(long)blk * EDIM + k] = __float2half_rn(src[k]);
    } else {
        int i = (blk - MTOT) * 256 + tid;
        if (i < BD * HDIM)
            g_h16[0][i] = __float2half(0.f);
        if (i < 8 * 64) {
            g_bar_cnt[i] = 0u;
            g_bar_gen[i] = 0u;
        }
    }
}

// prepB: blocks [0, NG): pack input W (fp16). Blocks [NG, 2*NG): recurrent W.
__global__ void k_prepB(const float* __restrict__ Wii, const float* __restrict__ Wif,
                        const float* __restrict__ Wig, const float* __restrict__ Wio,
                        const float* __restrict__ Whi, const float* __restrict__ Whf,
                        const float* __restrict__ Whg, const float* __restrict__ Who) {
    const int blk = blockIdx.x;
    if (blk < NG) {
        int n = blk;
        int g = n >> 10, col = n & 1023;
        const float* src = ((g == 0) ? Wii : (g == 1) ? Wif : (g == 2) ? Wig : Wio)
                           + (long)col * EDIM;
        for (int k = threadIdx.x; k < EDIM; k += blockDim.x)
            g_Wip[(long)n * EDIM + k] = __float2half_rn(src[k]);
    } else {
        int n = blk - NG;
        int hb = n >> 5, r = n & 31, g = r >> 3, j = r & 7;
        int h = hb * 8 + j;
        const float* src = ((g == 0) ? Whi : (g == 1) ? Whf : (g == 2) ? Whg : Who)
                           + (long)h * HDIM;
        for (int k = threadIdx.x; k < HDIM; k += blockDim.x)
            g_Whp[(long)n * HDIM + k] = __float2half_rn(src[k]);
    }
}

// ---------------------------------------------------------------------------
// Input projection GEMM: [32768 x 512] @ [512 x 4096], fp16 single-term.
// CTA tile 128x128, 256 threads, kc=16, 2-stage. Regions: A, B.
// ---------------------------------------------------------------------------
#define IP 24
__global__ __launch_bounds__(256)
void k_igemm_tc(const float* __restrict__ bi, const float* __restrict__ bf2,
                const float* __restrict__ bg, const float* __restrict__ bo) {
    __shared__ __align__(16) __half sm[2][2][128 * IP];

    const int tid = threadIdx.x;
    const int n0 = blockIdx.x * 128;
    const int M0 = blockIdx.y * 128;

    const int w = tid >> 5, lane = tid & 31;
    const int g = lane >> 2, tig = lane & 3;
    const int m0w = (w >> 1) * 32, n0w = (w & 1) * 64;

    // copy plan: 256 rows of 32B per stage, one per thread
    const int sel0 = tid >> 7, idx0 = tid & 127;
    const __half* gp0 = sel0 ? (g_Wip + (long)(n0 + idx0) * EDIM)
                             : (g_e16 + (long)(M0 + idx0) * EDIM);

    float acc[2][8][4];
#pragma unroll
    for (int mt = 0; mt < 2; mt++)
#pragma unroll
        for (int nt = 0; nt < 8; nt++)
#pragma unroll
            for (int q = 0; q < 4; q++) acc[mt][nt][q] = 0.f;

    uint4 p0[2];
    p0[0] = ((const uint4*)gp0)[0]; p0[1] = ((const uint4*)gp0)[1];
    {
        uint4* d = (uint4*)(&sm[0][sel0][idx0 * IP]);
        d[0] = p0[0]; d[1] = p0[1];
    }
    __syncthreads();

    const int NSTAGE = EDIM / 16;
    for (int s = 0; s < NSTAGE; s++) {
        int buf = s & 1;
        bool more = (s + 1 < NSTAGE);
        if (more) {
            gp0 += 16;
            p0[0] = ((const uint4*)gp0)[0]; p0[1] = ((const uint4*)gp0)[1];
        }
        const __half* Am = sm[buf][0];
        const __half* Bm = sm[buf][1];
        const int kb = 2 * tig;

        uint32_t aF[2][4], bF[8][2];
#pragma unroll
        for (int mt = 0; mt < 2; mt++) {
            int rw = (m0w + mt * 16 + g) * IP + kb;
            aF[mt][0] = *(const uint32_t*)(Am + rw);
            aF[mt][1] = *(const uint32_t*)(Am + rw + 8 * IP);
            aF[mt][2] = *(const uint32_t*)(Am + rw + 8);
            aF[mt][3] = *(const uint32_t*)(Am + rw + 8 * IP + 8);
        }
#pragma unroll
        for (int nt = 0; nt < 8; nt++) {
            int cw = (n0w + nt * 8 + g) * IP + kb;
            bF[nt][0] = *(const uint32_t*)(Bm + cw);
            bF[nt][1] = *(const uint32_t*)(Bm + cw + 8);
        }
#pragma unroll
        for (int mt = 0; mt < 2; mt++)
#pragma unroll
            for (int nt = 0; nt < 8; nt++) {
                float* d = acc[mt][nt];
                mma16816(d[0], d[1], d[2], d[3], aF[mt][0], aF[mt][1], aF[mt][2], aF[mt][3], bF[nt][0], bF[nt][1]);
            }

        if (more) {
            uint4* d = (uint4*)(&sm[buf ^ 1][sel0][idx0 * IP]);
            d[0] = p0[0]; d[1] = p0[1];
        }
        __syncthreads();
    }

#pragma unroll
    for (int mt = 0; mt < 2; mt++) {
        int r0 = m0w + mt * 16 + g;
#pragma unroll
        for (int nt = 0; nt < 8; nt++) {
            int col  = n0w + nt * 8 + 2 * tig;
            int ncol = n0 + col;
            int gate = ncol >> 10, hcol = ncol & 1023;
            int hb = hcol >> 3, j = hcol & 7;
            const float* bptr = (gate == 0) ? bi : (gate == 1) ? bf2 : (gate == 2) ? bg : bo;
            float bv0 = bptr[hcol], bv1 = bptr[hcol + 1];
#pragma unroll
            for (int hf = 0; hf < 2; hf++) {
                int mrow = M0 + r0 + hf * 8;
                int b = mrow >> 8, ss = mrow & 255;
                float2 v = make_float2(acc[mt][nt][hf * 2] + bv0, acc[mt][nt][hf * 2 + 1] + bv1);
                long off = ((((long)ss * 128 + hb) * 4 + gate) * 128 + b) * 8 + j;
                *(float2*)(g_gatesx + off) = v;
            }
        }
    }
}

// ---------------------------------------------------------------------------
// Persistent LSTM step kernel v6: split-K, single fp16 term, coalesced loads.
// ---------------------------------------------------------------------------
#define SM_A   0                       // 2 groups x 2 bufs x 16KB = 64KB
#define SM_W   65536                   // 64KB resident W
#define SM_R   (65536 + 65536)         // 16KB reduce
#define SMEM_TC6 (SM_R + 16384)        // 147456

__device__ __forceinline__ void gridbar(unsigned gen) {
    __syncthreads();
    if (threadIdx.x == 0) {
        __threadfence();
        int c = (blockIdx.x & 7) * 64;
        unsigned prev = atomicAdd(&g_bar_cnt[c], 1u);
        if (prev == (NCTA / 8) - 1) {
            g_bar_cnt[c] = 0u;
            __threadfence();
            g_bar_gen[c] = gen;
        }
    }
    if (threadIdx.x < 8) {
        while (g_bar_gen[threadIdx.x * 64] < gen) { }
        __threadfence();
    }
    __syncthreads();
}

__global__ __launch_bounds__(NTH, 1)
void k_step6() {
    extern __shared__ __align__(1024) unsigned char smraw[];
    const uint32_t sb = (uint32_t)__cvta_generic_to_shared(smraw);

    const int tid = threadIdx.x;
    const int cta = blockIdx.x;
    const int wid = tid >> 5, lane = tid & 31;
    const int g2 = wid >> 3;            // K-group
    const int wg = wid & 7;             // M-warp within group

    // ---- resident W (fp16, 32x1024) -> SMEM SW128 blocked-atom ----
    {
        const __half* wsrc = g_Whp + (long)cta * 32 * HDIM;
        unsigned char* wdst = smraw + SM_W;
        for (int idx = tid; idx < 32 * 128; idx += NTH) {
            int r = idx >> 7, cc = idx & 127;
            int c0 = cc * 8;
            uint32_t byte = (uint32_t)(((r >> 3) + (c0 >> 6) * 4) * 1024 + (r & 7) * 128 + (c0 & 63) * 2);
            *(uint4*)(wdst + SWZ128(byte)) = *(const uint4*)(wsrc + r * HDIM + c0);
        }
    }

    // ---- ldmatrix lane addresses ----
    const int aq = lane >> 3, al = lane & 7;
    const int am = wg * 16 + ((aq & 1) ? 8 : 0) + al;
    const uint32_t akb = (uint32_t)((aq >> 1) * 16);
    const uint32_t aR  = (uint32_t)((am >> 3) * 1024 + (am & 7) * 128);
    const uint32_t aC  = (uint32_t)((am & 7) * 16);
    const int bq = lane >> 3, bl = lane & 7;
    const int bn_off = (bq >> 1) * 8;
    const uint32_t bkb = (uint32_t)((bq & 1) * 16);
    uint32_t bR[2], bC[2];
#pragma unroll
    for (int p = 0; p < 2; p++) {
        int n = p * 16 + bn_off + bl;
        bR[p] = (uint32_t)((n >> 3) * 1024 + (n & 7) * 128);
        bC[p] = (uint32_t)((n & 7) * 16);
    }

    // ---- coalesced loader mapping ----
    // seg = tid&7 (16B segment), slot = (tid>>3)&31; thread loads rows
    // slot+32i (i=0..3). Warp-instr = 4 rows x 8 segs = 4 full 128B lines.
    const int seg  = tid & 7;
    const int slot = (tid >> 3) & 31;
    const uint32_t dst0 = (uint32_t)((slot >> 3) * 1024 + (slot & 7) * 128 + seg * 16);
    const uint32_t abase = sb + SM_A + (uint32_t)g2 * 32768;
    const int barid = 1 + g2;

    // epilogue mapping (group 0)
    const int er = lane >> 2, ec = (lane & 3) * 2;
    const int b0 = wg * 16 + er;
    const int ridx = wg * 32 + lane;
    float* sR = (float*)(smraw + SM_R);

    float creg[2][2];
    creg[0][0] = creg[0][1] = creg[1][0] = creg[1][1] = 0.f;

    __syncthreads();

    for (int t = 0; t < SLEN; t++) {
        const int par = t & 1, nxt = par ^ 1;
        const __half* srcH = g_h16[par] + (long)slot * HDIM + g2 * 512 + seg * 8;

        // prologue: chunks 0,1 of this group's K-half
#pragma unroll
        for (int c = 0; c < 2; c++) {
            uint32_t dst = abase + (uint32_t)c * 16384;
            const __half* sH = srcH + c * 64;
#pragma unroll
            for (int i = 0; i < 4; i++)
                cpa16(dst + SWZ128(dst0 + i * 4096), sH + i * 32 * HDIM);
            CP_COMMIT();
        }

        // gates preload into registers (group 0 only)
        float2 gv[4][2];
        if (g2 == 0) {
            const float* gx = g_gatesx + ((long)(t * 128 + cta) * 4) * 1024;
#pragma unroll
            for (int g = 0; g < 4; g++) {
                gv[g][0] = *(const float2*)(gx + (g * 128 + b0) * 8 + ec);
                gv[g][1] = *(const float2*)(gx + (g * 128 + b0 + 8) * 8 + ec);
            }
        }

        float acc[4][4];
#pragma unroll
        for (int nt = 0; nt < 4; nt++)
#pragma unroll
            for (int q = 0; q < 4; q++) acc[nt][q] = 0.f;

        for (int s = 0; s < 8; s++) {
            cp_wait<1>();
            BARG(barid);                       // chunk s visible group-wide

            const uint32_t aB = abase + (uint32_t)(s & 1) * 16384;
            const uint32_t wB = sb + SM_W + (uint32_t)(g2 * 8 + s) * 4096;

#pragma unroll
            for (int kt = 0; kt < 4; kt++) {
                const uint32_t ka = (uint32_t)(kt * 32);
                uint32_t ah[4];
                ldsm4(ah[0], ah[1], ah[2], ah[3], aB + aR + ((ka + akb) ^ aC));
#pragma unroll
                for (int p = 0; p < 2; p++) {
                    uint32_t bh[4];
                    ldsm4(bh[0], bh[1], bh[2], bh[3], wB + bR[p] + ((ka + bkb) ^ bC[p]));
#pragma unroll
                    for (int h2 = 0; h2 < 2; h2++) {
                        float* d = acc[p * 2 + h2];
                        mma16816(d[0], d[1], d[2], d[3], ah[0], ah[1], ah[2], ah[3], bh[h2 * 2], bh[h2 * 2 + 1]);
                    }
                }
            }

            BARG(barid);                       // all reads of buf (s&1) done
            if (s + 2 < 8) {
                uint32_t dst = abase + (uint32_t)(s & 1) * 16384;
                const __half* sH = srcH + (s + 2) * 64;
#pragma unroll
                for (int i = 0; i < 4; i++)
                    cpa16(dst + SWZ128(dst0 + i * 4096), sH + i * 32 * HDIM);
            }
            CP_COMMIT();
        }

        // reduce: group 1 -> SMEM
        if (g2 == 1) {
#pragma unroll
            for (int q = 0; q < 16; q++)
                sR[q * 256 + ridx] = acc[q >> 2][q & 3];
        }
        __syncthreads();

        if (g2 == 0) {
#pragma unroll
            for (int q = 0; q < 16; q++)
                acc[q >> 2][q & 3] += sR[q * 256 + ridx];

            // register-local cell update: rows b0, b0+8; cols cta*8+ec+{0,1}
#pragma unroll
            for (int h2 = 0; h2 < 2; h2++) {
                const int bb = b0 + h2 * 8;
                float hn[2];
                __half hh[2];
#pragma unroll
                for (int q = 0; q < 2; q++) {
                    float pi = acc[0][h2 * 2 + q] + (q ? gv[0][h2].y : gv[0][h2].x);
                    float pf = acc[1][h2 * 2 + q] + (q ? gv[1][h2].y : gv[1][h2].x);
                    float pg = acc[2][h2 * 2 + q] + (q ? gv[2][h2].y : gv[2][h2].x);
                    float po = acc[3][h2 * 2 + q] + (q ? gv[3][h2].y : gv[3][h2].x);
                    float iv = 1.f / (1.f + expf(-pi));
                    float fv = 1.f / (1.f + expf(-pf));
                    float gg = tanhf(pg);
                    float ov = 1.f / (1.f + expf(-po));
                    float cn = fv * creg[h2][q] + iv * gg;
                    creg[h2][q] = cn;
                    hn[q] = ov * tanhf(cn);
                    hh[q] = __float2half_rn(hn[q]);
                }
                long hb = (long)bb * HDIM + cta * 8 + ec;
                *(__half2*)&g_h16[nxt][hb] = *(__half2*)hh;
                if (t == SLEN - 1) *(float2*)&g_h[hb] = make_float2(hn[0], hn[1]);
            }
        }

        gridbar((unsigned)(t + 1));
    }
}

// ---------------------------------------------------------------------------
__global__ void k_fc(const float* __restrict__ fcW, const float* __restrict__ fcb,
                     float* __restrict__ out) {
    int b = blockIdx.x;
    int w = threadIdx.x >> 5, lane = threadIdx.x & 31;
    if (w >= ODIM) return;
    const float* hrow = g_h + b * HDIM;
    const float* wrow = fcW + w * HDIM;
    float s = 0.f;
    for (int k = lane; k < HDIM; k += 32) s += hrow[k] * wrow[k];
#pragma unroll
    for (int off = 16; off; off >>= 1) s += __shfl_xor_sync(0xffffffffu, s, off);
    if (lane == 0) out[b * ODIM + w] = s + fcb[w];
}

// ---------------------------------------------------------------------------
extern "C" void kernel_launch(void* const* d_in, const int* in_sizes, int n_in,
                              void* d_out, int out_size) {
    const void*  x   = d_in[0];
    const float* emb = (const float*)d_in[1];
    const float* Wii = (const float*)d_in[2];
    const float* bii = (const float*)d_in[3];
    const float* Whi = (const float*)d_in[4];
    const float* Wif = (const float*)d_in[5];
    const float* bif = (const float*)d_in[6];
    const float* Whf = (const float*)d_in[7];
    const float* Wig = (const float*)d_in[8];
    const float* big = (const float*)d_in[9];
    const float* Whg = (const float*)d_in[10];
    const float* Wio = (const float*)d_in[11];
    const float* bio = (const float*)d_in[12];
    const float* Who = (const float*)d_in[13];
    const float* fcW = (const float*)d_in[14];
    const float* fcb = (const float*)d_in[15];
    float* out = (float*)d_out;

    cudaFuncSetAttribute(k_step6, cudaFuncAttributeMaxDynamicSharedMemorySize,
                         SMEM_TC6);

    k_prepA<<<MTOT + 512, 256>>>(x, emb);
    k_prepB<<<2 * NG, 256>>>(Wii, Wif, Wig, Wio, Whi, Whf, Whg, Who);
    k_igemm_tc<<<dim3(NG / 128, MTOT / 128), 256>>>(bii, bif, big, bio);
    k_step6<<<NCTA, NTH, SMEM_TC6>>>();
    k_fc<<<BD, 320>>>(fcW, fcb, out);
}

// round 12
// speedup vs baseline: 3.0834x; 1.0374x over previous
#include <cuda_runtime.h>
#include <cuda_fp16.h>
#include <math.h>
#include <stdint.h>

// Problem dims
#define BD    128
#define SLEN  256
#define EDIM  512
#define HDIM  1024
#define ODIM  10
#define NG    4096
#define MTOT  (BD*SLEN)

#define NCTA  128
#define NTH   512     // 16 warps: 2 K-groups x 8 M-warps

// ---------------------------------------------------------------------------
// Device scratch
// ---------------------------------------------------------------------------
// gatesx layout: [s][hb(128)][g(4)][b(128)][8]
__device__ float g_gatesx[(long)SLEN * BD * NG];
__device__ float g_h[BD * HDIM];

__device__ __half g_h16[2][BD * HDIM];      // fp16 h, ping-pong
__device__ __half g_Whp[(long)NG * HDIM];   // fp16 W, n = cta*32 + g*8 + j
__device__ __half g_Wip[(long)NG * EDIM];   // fp16 W, n = g*1024 + col
__device__ __half g_e16[(long)MTOT * EDIM]; // fp16 gathered embeddings

__device__ unsigned          g_bar_cnt[8 * 64];
__device__ volatile unsigned g_bar_gen[8 * 64];

// ---------------------------------------------------------------------------
__device__ __forceinline__ void mma16816(float& d0, float& d1, float& d2, float& d3,
                                         uint32_t a0, uint32_t a1, uint32_t a2, uint32_t a3,
                                         uint32_t b0, uint32_t b1) {
    asm volatile("mma.sync.aligned.m16n8k16.row.col.f32.f16.f16.f32 "
                 "{%0,%1,%2,%3}, {%4,%5,%6,%7}, {%8,%9}, {%0,%1,%2,%3};"
                 : "+f"(d0), "+f"(d1), "+f"(d2), "+f"(d3)
                 : "r"(a0), "r"(a1), "r"(a2), "r"(a3), "r"(b0), "r"(b1));
}

__device__ __forceinline__ void ldsm4(uint32_t& r0, uint32_t& r1, uint32_t& r2,
                                      uint32_t& r3, uint32_t addr) {
    asm volatile("ldmatrix.sync.aligned.m8n8.x4.shared.b16 {%0,%1,%2,%3}, [%4];"
                 : "=r"(r0), "=r"(r1), "=r"(r2), "=r"(r3) : "r"(addr));
}

__device__ __forceinline__ void cpa16(uint32_t s, const void* g) {
    asm volatile("cp.async.cg.shared.global [%0], [%1], 16;\n" :: "r"(s), "l"(g));
}
#define CP_COMMIT() asm volatile("cp.async.commit_group;\n" ::: "memory")
template <int N> __device__ __forceinline__ void cp_wait() {
    asm volatile("cp.async.wait_group %0;\n" :: "n"(N) : "memory");
}
#define BARG(id) asm volatile("bar.sync %0, 256;" :: "r"(id) : "memory")

#define SWZ128(x) ((x) ^ (((x) >> 3) & 0x70))

// fast activations (__expf error ~1e-7 rel; negligible vs 3.5e-4 budget)
__device__ __forceinline__ float fsigmoid(float x) {
    return __fdividef(1.f, 1.f + __expf(-x));
}
__device__ __forceinline__ float ftanh(float x) {
    return 1.f - __fdividef(2.f, __expf(2.f * x) + 1.f);
}

// ---------------------------------------------------------------------------
// Merged prep (grid-stride): embedding gather+fp16, W packs, h/barrier init.
// ---------------------------------------------------------------------------
__global__ void k_prep(const void* __restrict__ xv, const float* __restrict__ emb,
                       const float* __restrict__ Wii, const float* __restrict__ Wif,
                       const float* __restrict__ Wig, const float* __restrict__ Wio,
                       const float* __restrict__ Whi, const float* __restrict__ Whf,
                       const float* __restrict__ Whg, const float* __restrict__ Who) {
    const int nb = gridDim.x, blk = blockIdx.x, tid = threadIdx.x;

    __shared__ int s64;
    if (tid == 0) {
        const int* xw = (const int*)xv;
        int zeros = 0;
        for (int i = 0; i < 64; i++)
            if (xw[2 * i + 1] == 0) zeros++;
        s64 = (zeros >= 60) ? 1 : 0;
    }
    __syncthreads();

    // embeddings
    for (int m = blk; m < MTOT; m += nb) {
        long tok = s64 ? (long)((const long long*)xv)[m] : (long)((const int*)xv)[m];
        const float* src = emb + tok * EDIM;
        for (int k = tid; k < EDIM; k += 256)
            g_e16[(long)m * EDIM + k] = __float2half_rn(src[k]);
    }
    // input W: n = g*1024 + col
    for (int n = blk; n < NG; n += nb) {
        int g = n >> 10, col = n & 1023;
        const float* src = ((g == 0) ? Wii : (g == 1) ? Wif : (g == 2) ? Wig : Wio)
                           + (long)col * EDIM;
        for (int k = tid; k < EDIM; k += 256)
            g_Wip[(long)n * EDIM + k] = __float2half_rn(src[k]);
    }
    // recurrent W: n = hb*32 + g*8 + j
    for (int n = blk; n < NG; n += nb) {
        int hb = n >> 5, r = n & 31, g = r >> 3, j = r & 7;
        int h = hb * 8 + j;
        const float* src = ((g == 0) ? Whi : (g == 1) ? Whf : (g == 2) ? Whg : Who)
                           + (long)h * HDIM;
        for (int k = tid; k < HDIM; k += 256)
            g_Whp[(long)n * HDIM + k] = __float2half_rn(src[k]);
    }
    // init h and barrier state
    for (int i = blk * 256 + tid; i < BD * HDIM; i += nb * 256)
        g_h16[0][i] = __float2half(0.f);
    for (int i = blk * 256 + tid; i < 8 * 64; i += nb * 256) {
        g_bar_cnt[i] = 0u;
        g_bar_gen[i] = 0u;
    }
}

// ---------------------------------------------------------------------------
// Input projection GEMM: [32768 x 512] @ [512 x 4096], fp16 single-term.
// ---------------------------------------------------------------------------
#define IP 24
__global__ __launch_bounds__(256)
void k_igemm_tc(const float* __restrict__ bi, const float* __restrict__ bf2,
                const float* __restrict__ bg, const float* __restrict__ bo) {
    __shared__ __align__(16) __half sm[2][2][128 * IP];

    const int tid = threadIdx.x;
    const int n0 = blockIdx.x * 128;
    const int M0 = blockIdx.y * 128;

    const int w = tid >> 5, lane = tid & 31;
    const int g = lane >> 2, tig = lane & 3;
    const int m0w = (w >> 1) * 32, n0w = (w & 1) * 64;

    const int sel0 = tid >> 7, idx0 = tid & 127;
    const __half* gp0 = sel0 ? (g_Wip + (long)(n0 + idx0) * EDIM)
                             : (g_e16 + (long)(M0 + idx0) * EDIM);

    float acc[2][8][4];
#pragma unroll
    for (int mt = 0; mt < 2; mt++)
#pragma unroll
        for (int nt = 0; nt < 8; nt++)
#pragma unroll
            for (int q = 0; q < 4; q++) acc[mt][nt][q] = 0.f;

    uint4 p0[2];
    p0[0] = ((const uint4*)gp0)[0]; p0[1] = ((const uint4*)gp0)[1];
    {
        uint4* d = (uint4*)(&sm[0][sel0][idx0 * IP]);
        d[0] = p0[0]; d[1] = p0[1];
    }
    __syncthreads();

    const int NSTAGE = EDIM / 16;
    for (int s = 0; s < NSTAGE; s++) {
        int buf = s & 1;
        bool more = (s + 1 < NSTAGE);
        if (more) {
            gp0 += 16;
            p0[0] = ((const uint4*)gp0)[0]; p0[1] = ((const uint4*)gp0)[1];
        }
        const __half* Am = sm[buf][0];
        const __half* Bm = sm[buf][1];
        const int kb = 2 * tig;

        uint32_t aF[2][4], bF[8][2];
#pragma unroll
        for (int mt = 0; mt < 2; mt++) {
            int rw = (m0w + mt * 16 + g) * IP + kb;
            aF[mt][0] = *(const uint32_t*)(Am + rw);
            aF[mt][1] = *(const uint32_t*)(Am + rw + 8 * IP);
            aF[mt][2] = *(const uint32_t*)(Am + rw + 8);
            aF[mt][3] = *(const uint32_t*)(Am + rw + 8 * IP + 8);
        }
#pragma unroll
        for (int nt = 0; nt < 8; nt++) {
            int cw = (n0w + nt * 8 + g) * IP + kb;
            bF[nt][0] = *(const uint32_t*)(Bm + cw);
            bF[nt][1] = *(const uint32_t*)(Bm + cw + 8);
        }
#pragma unroll
        for (int mt = 0; mt < 2; mt++)
#pragma unroll
            for (int nt = 0; nt < 8; nt++) {
                float* d = acc[mt][nt];
                mma16816(d[0], d[1], d[2], d[3], aF[mt][0], aF[mt][1], aF[mt][2], aF[mt][3], bF[nt][0], bF[nt][1]);
            }

        if (more) {
            uint4* d = (uint4*)(&sm[buf ^ 1][sel0][idx0 * IP]);
            d[0] = p0[0]; d[1] = p0[1];
        }
        __syncthreads();
    }

#pragma unroll
    for (int mt = 0; mt < 2; mt++) {
        int r0 = m0w + mt * 16 + g;
#pragma unroll
        for (int nt = 0; nt < 8; nt++) {
            int col  = n0w + nt * 8 + 2 * tig;
            int ncol = n0 + col;
            int gate = ncol >> 10, hcol = ncol & 1023;
            int hb = hcol >> 3, j = hcol & 7;
            const float* bptr = (gate == 0) ? bi : (gate == 1) ? bf2 : (gate == 2) ? bg : bo;
            float bv0 = bptr[hcol], bv1 = bptr[hcol + 1];
#pragma unroll
            for (int hf = 0; hf < 2; hf++) {
                int mrow = M0 + r0 + hf * 8;
                int b = mrow >> 8, ss = mrow & 255;
                float2 v = make_float2(acc[mt][nt][hf * 2] + bv0, acc[mt][nt][hf * 2 + 1] + bv1);
                long off = ((((long)ss * 128 + hb) * 4 + gate) * 128 + b) * 8 + j;
                *(float2*)(g_gatesx + off) = v;
            }
        }
    }
}

// ---------------------------------------------------------------------------
// Persistent LSTM step kernel (R10-proven skeleton): split-K, 2-buf ring,
// 2 barriers/chunk, 8-counter gridbar; fast-math epilogue.
// ---------------------------------------------------------------------------
#define SM_A   0                       // 2 groups x 2 bufs x 16KB = 64KB
#define SM_W   65536                   // 64KB resident W
#define SM_R   (65536 + 65536)         // 16KB reduce
#define SMEM_TC6 (SM_R + 16384)        // 147456

__device__ __forceinline__ void gridbar(unsigned gen) {
    __syncthreads();
    if (threadIdx.x == 0) {
        __threadfence();
        int c = (blockIdx.x & 7) * 64;
        unsigned prev = atomicAdd(&g_bar_cnt[c], 1u);
        if (prev == (NCTA / 8) - 1) {
            g_bar_cnt[c] = 0u;
            __threadfence();
            g_bar_gen[c] = gen;
        }
    }
    if (threadIdx.x < 8) {
        while (g_bar_gen[threadIdx.x * 64] < gen) { }
        __threadfence();
    }
    __syncthreads();
}

__global__ __launch_bounds__(NTH, 1)
void k_step6() {
    extern __shared__ __align__(1024) unsigned char smraw[];
    const uint32_t sb = (uint32_t)__cvta_generic_to_shared(smraw);

    const int tid = threadIdx.x;
    const int cta = blockIdx.x;
    const int wid = tid >> 5, lane = tid & 31;
    const int g2 = wid >> 3;            // K-group
    const int wg = wid & 7;             // M-warp within group

    // ---- resident W (fp16, 32x1024) -> SMEM SW128 blocked-atom ----
    {
        const __half* wsrc = g_Whp + (long)cta * 32 * HDIM;
        unsigned char* wdst = smraw + SM_W;
        for (int idx = tid; idx < 32 * 128; idx += NTH) {
            int r = idx >> 7, cc = idx & 127;
            int c0 = cc * 8;
            uint32_t byte = (uint32_t)(((r >> 3) + (c0 >> 6) * 4) * 1024 + (r & 7) * 128 + (c0 & 63) * 2);
            *(uint4*)(wdst + SWZ128(byte)) = *(const uint4*)(wsrc + r * HDIM + c0);
        }
    }

    // ---- ldmatrix lane addresses ----
    const int aq = lane >> 3, al = lane & 7;
    const int am = wg * 16 + ((aq & 1) ? 8 : 0) + al;
    const uint32_t akb = (uint32_t)((aq >> 1) * 16);
    const uint32_t aR  = (uint32_t)((am >> 3) * 1024 + (am & 7) * 128);
    const uint32_t aC  = (uint32_t)((am & 7) * 16);
    const int bq = lane >> 3, bl = lane & 7;
    const int bn_off = (bq >> 1) * 8;
    const uint32_t bkb = (uint32_t)((bq & 1) * 16);
    uint32_t bR[2], bC[2];
#pragma unroll
    for (int p = 0; p < 2; p++) {
        int n = p * 16 + bn_off + bl;
        bR[p] = (uint32_t)((n >> 3) * 1024 + (n & 7) * 128);
        bC[p] = (uint32_t)((n & 7) * 16);
    }

    // ---- coalesced loader mapping ----
    const int seg  = tid & 7;
    const int slot = (tid >> 3) & 31;
    const uint32_t dst0 = (uint32_t)((slot >> 3) * 1024 + (slot & 7) * 128 + seg * 16);
    const uint32_t abase = sb + SM_A + (uint32_t)g2 * 32768;
    const int barid = 1 + g2;

    // epilogue mapping (group 0)
    const int er = lane >> 2, ec = (lane & 3) * 2;
    const int b0 = wg * 16 + er;
    const int ridx = wg * 32 + lane;
    float* sR = (float*)(smraw + SM_R);

    float creg[2][2];
    creg[0][0] = creg[0][1] = creg[1][0] = creg[1][1] = 0.f;

    __syncthreads();

    for (int t = 0; t < SLEN; t++) {
        const int par = t & 1, nxt = par ^ 1;
        const __half* srcH = g_h16[par] + (long)slot * HDIM + g2 * 512 + seg * 8;

        // prologue: chunks 0,1 of this group's K-half
#pragma unroll
        for (int c = 0; c < 2; c++) {
            uint32_t dst = abase + (uint32_t)c * 16384;
            const __half* sH = srcH + c * 64;
#pragma unroll
            for (int i = 0; i < 4; i++)
                cpa16(dst + SWZ128(dst0 + i * 4096), sH + i * 32 * HDIM);
            CP_COMMIT();
        }

        // gates preload into registers (group 0 only)
        float2 gv[4][2];
        if (g2 == 0) {
            const float* gx = g_gatesx + ((long)(t * 128 + cta) * 4) * 1024;
#pragma unroll
            for (int g = 0; g < 4; g++) {
                gv[g][0] = *(const float2*)(gx + (g * 128 + b0) * 8 + ec);
                gv[g][1] = *(const float2*)(gx + (g * 128 + b0 + 8) * 8 + ec);
            }
        }

        float acc[4][4];
#pragma unroll
        for (int nt = 0; nt < 4; nt++)
#pragma unroll
            for (int q = 0; q < 4; q++) acc[nt][q] = 0.f;

        for (int s = 0; s < 8; s++) {
            cp_wait<1>();
            BARG(barid);                       // chunk s visible group-wide

            const uint32_t aB = abase + (uint32_t)(s & 1) * 16384;
            const uint32_t wB = sb + SM_W + (uint32_t)(g2 * 8 + s) * 4096;

#pragma unroll
            for (int kt = 0; kt < 4; kt++) {
                const uint32_t ka = (uint32_t)(kt * 32);
                uint32_t ah[4];
                ldsm4(ah[0], ah[1], ah[2], ah[3], aB + aR + ((ka + akb) ^ aC));
#pragma unroll
                for (int p = 0; p < 2; p++) {
                    uint32_t bh[4];
                    ldsm4(bh[0], bh[1], bh[2], bh[3], wB + bR[p] + ((ka + bkb) ^ bC[p]));
#pragma unroll
                    for (int h2 = 0; h2 < 2; h2++) {
                        float* d = acc[p * 2 + h2];
                        mma16816(d[0], d[1], d[2], d[3], ah[0], ah[1], ah[2], ah[3], bh[h2 * 2], bh[h2 * 2 + 1]);
                    }
                }
            }

            BARG(barid);                       // all reads of buf (s&1) done
            if (s + 2 < 8) {
                uint32_t dst = abase + (uint32_t)(s & 1) * 16384;
                const __half* sH = srcH + (s + 2) * 64;
#pragma unroll
                for (int i = 0; i < 4; i++)
                    cpa16(dst + SWZ128(dst0 + i * 4096), sH + i * 32 * HDIM);
            }
            CP_COMMIT();
        }

        // reduce: group 1 -> SMEM
        if (g2 == 1) {
#pragma unroll
            for (int q = 0; q < 16; q++)
                sR[q * 256 + ridx] = acc[q >> 2][q & 3];
        }
        __syncthreads();

        if (g2 == 0) {
#pragma unroll
            for (int q = 0; q < 16; q++)
                acc[q >> 2][q & 3] += sR[q * 256 + ridx];

            // register-local cell update: rows b0, b0+8; cols cta*8+ec+{0,1}
#pragma unroll
            for (int h2 = 0; h2 < 2; h2++) {
                const int bb = b0 + h2 * 8;
                float hn[2];
                __half hh[2];
#pragma unroll
                for (int q = 0; q < 2; q++) {
                    float pi = acc[0][h2 * 2 + q] + (q ? gv[0][h2].y : gv[0][h2].x);
                    float pf = acc[1][h2 * 2 + q] + (q ? gv[1][h2].y : gv[1][h2].x);
                    float pg = acc[2][h2 * 2 + q] + (q ? gv[2][h2].y : gv[2][h2].x);
                    float po = acc[3][h2 * 2 + q] + (q ? gv[3][h2].y : gv[3][h2].x);
                    float iv = fsigmoid(pi);
                    float fv = fsigmoid(pf);
                    float gg = ftanh(pg);
                    float ov = fsigmoid(po);
                    float cn = fv * creg[h2][q] + iv * gg;
                    creg[h2][q] = cn;
                    hn[q] = ov * ftanh(cn);
                    hh[q] = __float2half_rn(hn[q]);
                }
                long hb = (long)bb * HDIM + cta * 8 + ec;
                *(__half2*)&g_h16[nxt][hb] = *(__half2*)hh;
                if (t == SLEN - 1) *(float2*)&g_h[hb] = make_float2(hn[0], hn[1]);
            }
        }

        gridbar((unsigned)(t + 1));
    }
}

// ---------------------------------------------------------------------------
__global__ void k_fc(const float* __restrict__ fcW, const float* __restrict__ fcb,
                     float* __restrict__ out) {
    int b = blockIdx.x;
    int w = threadIdx.x >> 5, lane = threadIdx.x & 31;
    if (w >= ODIM) return;
    const float* hrow = g_h + b * HDIM;
    const float* wrow = fcW + w * HDIM;
    float s = 0.f;
    for (int k = lane; k < HDIM; k += 32) s += hrow[k] * wrow[k];
#pragma unroll
    for (int off = 16; off; off >>= 1) s += __shfl_xor_sync(0xffffffffu, s, off);
    if (lane == 0) out[b * ODIM + w] = s + fcb[w];
}

// ---------------------------------------------------------------------------
extern "C" void kernel_launch(void* const* d_in, const int* in_sizes, int n_in,
                              void* d_out, int out_size) {
    const void*  x   = d_in[0];
    const float* emb = (const float*)d_in[1];
    const float* Wii = (const float*)d_in[2];
    const float* bii = (const float*)d_in[3];
    const float* Whi = (const float*)d_in[4];
    const float* Wif = (const float*)d_in[5];
    const float* bif = (const float*)d_in[6];
    const float* Whf = (const float*)d_in[7];
    const float* Wig = (const float*)d_in[8];
    const float* big = (const float*)d_in[9];
    const float* Whg = (const float*)d_in[10];
    const float* Wio = (const float*)d_in[11];
    const float* bio = (const float*)d_in[12];
    const float* Who = (const float*)d_in[13];
    const float* fcW = (const float*)d_in[14];
    const float* fcb = (const float*)d_in[15];
    float* out = (float*)d_out;

    cudaFuncSetAttribute(k_step6, cudaFuncAttributeMaxDynamicSharedMemorySize,
                         SMEM_TC6);

    k_prep<<<2048, 256>>>(x, emb, Wii, Wif, Wig, Wio, Whi, Whf, Whg, Who);
    k_igemm_tc<<<dim3(NG / 128, MTOT / 128), 256>>>(bii, bif, big, bio);
    k_step6<<<NCTA, NTH, SMEM_TC6>>>();
    k_fc<<<BD, 320>>>(fcW, fcb, out);
}

// round 13
// speedup vs baseline: 3.1327x; 1.0160x over previous
#include <cuda_runtime.h>
#include <cuda_fp16.h>
#include <math.h>
#include <stdint.h>

// Problem dims
#define BD    128
#define SLEN  256
#define EDIM  512
#define HDIM  1024
#define ODIM  10
#define NG    4096
#define MTOT  (BD*SLEN)

#define NCTA  128
#define NTH   512     // 16 warps: 2 K-groups x 8 M-warps

// ---------------------------------------------------------------------------
// Device scratch
// ---------------------------------------------------------------------------
// gatesx layout: [s][hb(128)][g(4)][b(128)][8]
__device__ float g_gatesx[(long)SLEN * BD * NG];
__device__ float g_h[BD * HDIM];

__device__ __half g_h16[2][BD * HDIM];      // fp16 h, ping-pong
__device__ __half g_Whp[(long)NG * HDIM];   // fp16 W, n = cta*32 + g*8 + j
__device__ __half g_Wip[(long)NG * EDIM];   // fp16 W, n = g*1024 + col
__device__ __half g_e16[(long)MTOT * EDIM]; // fp16 gathered embeddings

__device__ unsigned          g_bar_cnt[8 * 64];
__device__ volatile unsigned g_bar_gen[8 * 64];

// ---------------------------------------------------------------------------
__device__ __forceinline__ void mma16816(float& d0, float& d1, float& d2, float& d3,
                                         uint32_t a0, uint32_t a1, uint32_t a2, uint32_t a3,
                                         uint32_t b0, uint32_t b1) {
    asm volatile("mma.sync.aligned.m16n8k16.row.col.f32.f16.f16.f32 "
                 "{%0,%1,%2,%3}, {%4,%5,%6,%7}, {%8,%9}, {%0,%1,%2,%3};"
                 : "+f"(d0), "+f"(d1), "+f"(d2), "+f"(d3)
                 : "r"(a0), "r"(a1), "r"(a2), "r"(a3), "r"(b0), "r"(b1));
}

__device__ __forceinline__ void ldsm4(uint32_t& r0, uint32_t& r1, uint32_t& r2,
                                      uint32_t& r3, uint32_t addr) {
    asm volatile("ldmatrix.sync.aligned.m8n8.x4.shared.b16 {%0,%1,%2,%3}, [%4];"
                 : "=r"(r0), "=r"(r1), "=r"(r2), "=r"(r3) : "r"(addr));
}

__device__ __forceinline__ void cpa16(uint32_t s, const void* g) {
    asm volatile("cp.async.cg.shared.global [%0], [%1], 16;\n" :: "r"(s), "l"(g));
}
#define CP_COMMIT() asm volatile("cp.async.commit_group;\n" ::: "memory")
template <int N> __device__ __forceinline__ void cp_wait() {
    asm volatile("cp.async.wait_group %0;\n" :: "n"(N) : "memory");
}
#define BARG(id) asm volatile("bar.sync %0, 256;" :: "r"(id) : "memory")

#define SWZ128(x) ((x) ^ (((x) >> 3) & 0x70))

// fast activations (__expf error ~1e-7 rel; negligible vs 3.5e-4 budget)
__device__ __forceinline__ float fsigmoid(float x) {
    return __fdividef(1.f, 1.f + __expf(-x));
}
__device__ __forceinline__ float ftanh(float x) {
    return 1.f - __fdividef(2.f, __expf(2.f * x) + 1.f);
}

// ---------------------------------------------------------------------------
// Merged prep (grid-stride): embedding gather+fp16, W packs, h/barrier init.
// ---------------------------------------------------------------------------
__global__ void k_prep(const void* __restrict__ xv, const float* __restrict__ emb,
                       const float* __restrict__ Wii, const float* __restrict__ Wif,
                       const float* __restrict__ Wig, const float* __restrict__ Wio,
                       const float* __restrict__ Whi, const float* __restrict__ Whf,
                       const float* __restrict__ Whg, const float* __restrict__ Who) {
    const int nb = gridDim.x, blk = blockIdx.x, tid = threadIdx.x;

    __shared__ int s64;
    if (tid == 0) {
        const int* xw = (const int*)xv;
        int zeros = 0;
        for (int i = 0; i < 64; i++)
            if (xw[2 * i + 1] == 0) zeros++;
        s64 = (zeros >= 60) ? 1 : 0;
    }
    __syncthreads();

    // embeddings
    for (int m = blk; m < MTOT; m += nb) {
        long tok = s64 ? (long)((const long long*)xv)[m] : (long)((const int*)xv)[m];
        const float* src = emb + tok * EDIM;
        for (int k = tid; k < EDIM; k += 256)
            g_e16[(long)m * EDIM + k] = __float2half_rn(src[k]);
    }
    // input W: n = g*1024 + col
    for (int n = blk; n < NG; n += nb) {
        int g = n >> 10, col = n & 1023;
        const float* src = ((g == 0) ? Wii : (g == 1) ? Wif : (g == 2) ? Wig : Wio)
                           + (long)col * EDIM;
        for (int k = tid; k < EDIM; k += 256)
            g_Wip[(long)n * EDIM + k] = __float2half_rn(src[k]);
    }
    // recurrent W: n = hb*32 + g*8 + j
    for (int n = blk; n < NG; n += nb) {
        int hb = n >> 5, r = n & 31, g = r >> 3, j = r & 7;
        int h = hb * 8 + j;
        const float* src = ((g == 0) ? Whi : (g == 1) ? Whf : (g == 2) ? Whg : Who)
                           + (long)h * HDIM;
        for (int k = tid; k < HDIM; k += 256)
            g_Whp[(long)n * HDIM + k] = __float2half_rn(src[k]);
    }
    // init h and barrier state
    for (int i = blk * 256 + tid; i < BD * HDIM; i += nb * 256)
        g_h16[0][i] = __float2half(0.f);
    for (int i = blk * 256 + tid; i < 8 * 64; i += nb * 256) {
        g_bar_cnt[i] = 0u;
        g_bar_gen[i] = 0u;
    }
}

// ---------------------------------------------------------------------------
// Input projection GEMM: [32768 x 512] @ [512 x 4096], fp16 single-term.
// ---------------------------------------------------------------------------
#define IP 24
__global__ __launch_bounds__(256)
void k_igemm_tc(const float* __restrict__ bi, const float* __restrict__ bf2,
                const float* __restrict__ bg, const float* __restrict__ bo) {
    __shared__ __align__(16) __half sm[2][2][128 * IP];

    const int tid = threadIdx.x;
    const int n0 = blockIdx.x * 128;
    const int M0 = blockIdx.y * 128;

    const int w = tid >> 5, lane = tid & 31;
    const int g = lane >> 2, tig = lane & 3;
    const int m0w = (w >> 1) * 32, n0w = (w & 1) * 64;

    const int sel0 = tid >> 7, idx0 = tid & 127;
    const __half* gp0 = sel0 ? (g_Wip + (long)(n0 + idx0) * EDIM)
                             : (g_e16 + (long)(M0 + idx0) * EDIM);

    float acc[2][8][4];
#pragma unroll
    for (int mt = 0; mt < 2; mt++)
#pragma unroll
        for (int nt = 0; nt < 8; nt++)
#pragma unroll
            for (int q = 0; q < 4; q++) acc[mt][nt][q] = 0.f;

    uint4 p0[2];
    p0[0] = ((const uint4*)gp0)[0]; p0[1] = ((const uint4*)gp0)[1];
    {
        uint4* d = (uint4*)(&sm[0][sel0][idx0 * IP]);
        d[0] = p0[0]; d[1] = p0[1];
    }
    __syncthreads();

    const int NSTAGE = EDIM / 16;
    for (int s = 0; s < NSTAGE; s++) {
        int buf = s & 1;
        bool more = (s + 1 < NSTAGE);
        if (more) {
            gp0 += 16;
            p0[0] = ((const uint4*)gp0)[0]; p0[1] = ((const uint4*)gp0)[1];
        }
        const __half* Am = sm[buf][0];
        const __half* Bm = sm[buf][1];
        const int kb = 2 * tig;

        uint32_t aF[2][4], bF[8][2];
#pragma unroll
        for (int mt = 0; mt < 2; mt++) {
            int rw = (m0w + mt * 16 + g) * IP + kb;
            aF[mt][0] = *(const uint32_t*)(Am + rw);
            aF[mt][1] = *(const uint32_t*)(Am + rw + 8 * IP);
            aF[mt][2] = *(const uint32_t*)(Am + rw + 8);
            aF[mt][3] = *(const uint32_t*)(Am + rw + 8 * IP + 8);
        }
#pragma unroll
        for (int nt = 0; nt < 8; nt++) {
            int cw = (n0w + nt * 8 + g) * IP + kb;
            bF[nt][0] = *(const uint32_t*)(Bm + cw);
            bF[nt][1] = *(const uint32_t*)(Bm + cw + 8);
        }
#pragma unroll
        for (int mt = 0; mt < 2; mt++)
#pragma unroll
            for (int nt = 0; nt < 8; nt++) {
                float* d = acc[mt][nt];
                mma16816(d[0], d[1], d[2], d[3], aF[mt][0], aF[mt][1], aF[mt][2], aF[mt][3], bF[nt][0], bF[nt][1]);
            }

        if (more) {
            uint4* d = (uint4*)(&sm[buf ^ 1][sel0][idx0 * IP]);
            d[0] = p0[0]; d[1] = p0[1];
        }
        __syncthreads();
    }

#pragma unroll
    for (int mt = 0; mt < 2; mt++) {
        int r0 = m0w + mt * 16 + g;
#pragma unroll
        for (int nt = 0; nt < 8; nt++) {
            int col  = n0w + nt * 8 + 2 * tig;
            int ncol = n0 + col;
            int gate = ncol >> 10, hcol = ncol & 1023;
            int hb = hcol >> 3, j = hcol & 7;
            const float* bptr = (gate == 0) ? bi : (gate == 1) ? bf2 : (gate == 2) ? bg : bo;
            float bv0 = bptr[hcol], bv1 = bptr[hcol + 1];
#pragma unroll
            for (int hf = 0; hf < 2; hf++) {
                int mrow = M0 + r0 + hf * 8;
                int b = mrow >> 8, ss = mrow & 255;
                float2 v = make_float2(acc[mt][nt][hf * 2] + bv0, acc[mt][nt][hf * 2 + 1] + bv1);
                long off = ((((long)ss * 128 + hb) * 4 + gate) * 128 + b) * 8 + j;
                *(float2*)(g_gatesx + off) = v;
            }
        }
    }
}

// ---------------------------------------------------------------------------
// Persistent LSTM step kernel v8: kc=128 chunks (4/step), R10-proven sync
// pattern (2-buf ring, 2 BARGs per chunk, 8-counter gridbar).
// ---------------------------------------------------------------------------
#define SM_A   0                       // 2 groups x 2 bufs x 32KB = 128KB
#define SM_W   131072                  // 64KB resident W
#define SM_R   (131072 + 65536)        // 16KB reduce
#define SMEM_TC8 (SM_R + 16384)        // 212992

__device__ __forceinline__ void gridbar(unsigned gen) {
    __syncthreads();
    if (threadIdx.x == 0) {
        __threadfence();
        int c = (blockIdx.x & 7) * 64;
        unsigned prev = atomicAdd(&g_bar_cnt[c], 1u);
        if (prev == (NCTA / 8) - 1) {
            g_bar_cnt[c] = 0u;
            __threadfence();
            g_bar_gen[c] = gen;
        }
    }
    if (threadIdx.x < 8) {
        while (g_bar_gen[threadIdx.x * 64] < gen) { }
        __threadfence();
    }
    __syncthreads();
}

__global__ __launch_bounds__(NTH, 1)
void k_step8() {
    extern __shared__ __align__(1024) unsigned char smraw[];
    const uint32_t sb = (uint32_t)__cvta_generic_to_shared(smraw);

    const int tid = threadIdx.x;
    const int cta = blockIdx.x;
    const int wid = tid >> 5, lane = tid & 31;
    const int g2 = wid >> 3;            // K-group
    const int wg = wid & 7;             // M-warp within group

    // ---- resident W (fp16, 32x1024) -> SMEM SW128 blocked-atom ----
    {
        const __half* wsrc = g_Whp + (long)cta * 32 * HDIM;
        unsigned char* wdst = smraw + SM_W;
        for (int idx = tid; idx < 32 * 128; idx += NTH) {
            int r = idx >> 7, cc = idx & 127;
            int c0 = cc * 8;
            uint32_t byte = (uint32_t)(((r >> 3) + (c0 >> 6) * 4) * 1024 + (r & 7) * 128 + (c0 & 63) * 2);
            *(uint4*)(wdst + SWZ128(byte)) = *(const uint4*)(wsrc + r * HDIM + c0);
        }
    }

    // ---- ldmatrix lane addresses ----
    const int aq = lane >> 3, al = lane & 7;
    const int am = wg * 16 + ((aq & 1) ? 8 : 0) + al;
    const uint32_t akb = (uint32_t)((aq >> 1) * 16);
    const uint32_t aR  = (uint32_t)((am >> 3) * 1024 + (am & 7) * 128);
    const uint32_t aC  = (uint32_t)((am & 7) * 16);
    const int bq = lane >> 3, bl = lane & 7;
    const int bn_off = (bq >> 1) * 8;
    const uint32_t bkb = (uint32_t)((bq & 1) * 16);
    uint32_t bR[2], bC[2];
#pragma unroll
    for (int p = 0; p < 2; p++) {
        int n = p * 16 + bn_off + bl;
        bR[p] = (uint32_t)((n >> 3) * 1024 + (n & 7) * 128);
        bC[p] = (uint32_t)((n & 7) * 16);
    }

    // ---- coalesced loader mapping ----
    // seg = tid&7 (16B segment), slot = (tid>>3)&31; thread loads rows
    // slot+32i (i=0..3), two 64-col halves per kc=128 chunk.
    const int seg  = tid & 7;
    const int slot = (tid >> 3) & 31;
    const uint32_t dst0 = (uint32_t)((slot >> 3) * 1024 + (slot & 7) * 128 + seg * 16);
    const uint32_t abase = sb + SM_A + (uint32_t)g2 * 65536;   // 2 bufs x 32KB
    const int barid = 1 + g2;

    // epilogue mapping (group 0)
    const int er = lane >> 2, ec = (lane & 3) * 2;
    const int b0 = wg * 16 + er;
    const int ridx = wg * 32 + lane;
    float* sR = (float*)(smraw + SM_R);

    float creg[2][2];
    creg[0][0] = creg[0][1] = creg[1][0] = creg[1][1] = 0.f;

    __syncthreads();

    for (int t = 0; t < SLEN; t++) {
        const int par = t & 1, nxt = par ^ 1;
        const __half* srcH = g_h16[par] + (long)slot * HDIM + g2 * 512 + seg * 8;

        // prologue: chunks 0,1 (kc=128 each) into bufs 0,1
#pragma unroll
        for (int c = 0; c < 2; c++) {
            uint32_t dst = abase + (uint32_t)c * 32768;
            const __half* sH = srcH + c * 128;
#pragma unroll
            for (int hf = 0; hf < 2; hf++)
#pragma unroll
                for (int i = 0; i < 4; i++)
                    cpa16(dst + (uint32_t)hf * 16384 + SWZ128(dst0 + i * 4096),
                          sH + hf * 64 + i * 32 * HDIM);
            CP_COMMIT();
        }

        // gates preload into registers (group 0 only)
        float2 gv[4][2];
        if (g2 == 0) {
            const float* gx = g_gatesx + ((long)(t * 128 + cta) * 4) * 1024;
#pragma unroll
            for (int g = 0; g < 4; g++) {
                gv[g][0] = *(const float2*)(gx + (g * 128 + b0) * 8 + ec);
                gv[g][1] = *(const float2*)(gx + (g * 128 + b0 + 8) * 8 + ec);
            }
        }

        float acc[4][4];
#pragma unroll
        for (int nt = 0; nt < 4; nt++)
#pragma unroll
            for (int q = 0; q < 4; q++) acc[nt][q] = 0.f;

        for (int s = 0; s < 4; s++) {
            cp_wait<1>();
            BARG(barid);                       // chunk s visible group-wide

            const uint32_t aB = abase + (uint32_t)(s & 1) * 32768;
            const uint32_t wB = sb + SM_W + (uint32_t)(g2 * 8 + s * 2) * 4096;

#pragma unroll
            for (int kt = 0; kt < 8; kt++) {
                const uint32_t hf = (uint32_t)(kt >> 2);
                const uint32_t ka = (uint32_t)((kt & 3) * 32);
                uint32_t ah[4];
                ldsm4(ah[0], ah[1], ah[2], ah[3],
                      aB + hf * 16384 + aR + ((ka + akb) ^ aC));
#pragma unroll
                for (int p = 0; p < 2; p++) {
                    uint32_t bh[4];
                    ldsm4(bh[0], bh[1], bh[2], bh[3],
                          wB + hf * 4096 + bR[p] + ((ka + bkb) ^ bC[p]));
#pragma unroll
                    for (int h2 = 0; h2 < 2; h2++) {
                        float* d = acc[p * 2 + h2];
                        mma16816(d[0], d[1], d[2], d[3], ah[0], ah[1], ah[2], ah[3], bh[h2 * 2], bh[h2 * 2 + 1]);
                    }
                }
            }

            BARG(barid);                       // all reads of buf (s&1) done
            if (s + 2 < 4) {
                uint32_t dst = abase + (uint32_t)(s & 1) * 32768;
                const __half* sH = srcH + (s + 2) * 128;
#pragma unroll
                for (int hf = 0; hf < 2; hf++)
#pragma unroll
                    for (int i = 0; i < 4; i++)
                        cpa16(dst + (uint32_t)hf * 16384 + SWZ128(dst0 + i * 4096),
                              sH + hf * 64 + i * 32 * HDIM);
            }
            CP_COMMIT();
        }

        // reduce: group 1 -> SMEM
        if (g2 == 1) {
#pragma unroll
            for (int q = 0; q < 16; q++)
                sR[q * 256 + ridx] = acc[q >> 2][q & 3];
        }
        __syncthreads();

        if (g2 == 0) {
#pragma unroll
            for (int q = 0; q < 16; q++)
                acc[q >> 2][q & 3] += sR[q * 256 + ridx];

            // register-local cell update: rows b0, b0+8; cols cta*8+ec+{0,1}
#pragma unroll
            for (int h2 = 0; h2 < 2; h2++) {
                const int bb = b0 + h2 * 8;
                float hn[2];
                __half hh[2];
#pragma unroll
                for (int q = 0; q < 2; q++) {
                    float pi = acc[0][h2 * 2 + q] + (q ? gv[0][h2].y : gv[0][h2].x);
                    float pf = acc[1][h2 * 2 + q] + (q ? gv[1][h2].y : gv[1][h2].x);
                    float pg = acc[2][h2 * 2 + q] + (q ? gv[2][h2].y : gv[2][h2].x);
                    float po = acc[3][h2 * 2 + q] + (q ? gv[3][h2].y : gv[3][h2].x);
                    float iv = fsigmoid(pi);
                    float fv = fsigmoid(pf);
                    float gg = ftanh(pg);
                    float ov = fsigmoid(po);
                    float cn = fv * creg[h2][q] + iv * gg;
                    creg[h2][q] = cn;
                    hn[q] = ov * ftanh(cn);
                    hh[q] = __float2half_rn(hn[q]);
                }
                long hb = (long)bb * HDIM + cta * 8 + ec;
                *(__half2*)&g_h16[nxt][hb] = *(__half2*)hh;
                if (t == SLEN - 1) *(float2*)&g_h[hb] = make_float2(hn[0], hn[1]);
            }
        }

        gridbar((unsigned)(t + 1));
    }
}

// ---------------------------------------------------------------------------
__global__ void k_fc(const float* __restrict__ fcW, const float* __restrict__ fcb,
                     float* __restrict__ out) {
    int b = blockIdx.x;
    int w = threadIdx.x >> 5, lane = threadIdx.x & 31;
    if (w >= ODIM) return;
    const float* hrow = g_h + b * HDIM;
    const float* wrow = fcW + w * HDIM;
    float s = 0.f;
    for (int k = lane; k < HDIM; k += 32) s += hrow[k] * wrow[k];
#pragma unroll
    for (int off = 16; off; off >>= 1) s += __shfl_xor_sync(0xffffffffu, s, off);
    if (lane == 0) out[b * ODIM + w] = s + fcb[w];
}

// ---------------------------------------------------------------------------
extern "C" void kernel_launch(void* const* d_in, const int* in_sizes, int n_in,
                              void* d_out, int out_size) {
    const void*  x   = d_in[0];
    const float* emb = (const float*)d_in[1];
    const float* Wii = (const float*)d_in[2];
    const float* bii = (const float*)d_in[3];
    const float* Whi = (const float*)d_in[4];
    const float* Wif = (const float*)d_in[5];
    const float* bif = (const float*)d_in[6];
    const float* Whf = (const float*)d_in[7];
    const float* Wig = (const float*)d_in[8];
    const float* big = (const float*)d_in[9];
    const float* Whg = (const float*)d_in[10];
    const float* Wio = (const float*)d_in[11];
    const float* bio = (const float*)d_in[12];
    const float* Who = (const float*)d_in[13];
    const float* fcW = (const float*)d_in[14];
    const float* fcb = (const float*)d_in[15];
    float* out = (float*)d_out;

    cudaFuncSetAttribute(k_step8, cudaFuncAttributeMaxDynamicSharedMemorySize,
                         SMEM_TC8);

    k_prep<<<2048, 256>>>(x, emb, Wii, Wif, Wig, Wio, Whi, Whf, Whg, Who);
    k_igemm_tc<<<dim3(NG / 128, MTOT / 128), 256>>>(bii, bif, big, bio);
    k_step8<<<NCTA, NTH, SMEM_TC8>>>();
    k_fc<<<BD, 320>>>(fcW, fcb, out);
}